// round 1
// baseline (speedup 1.0000x reference)
#include <cuda_runtime.h>
#include <math.h>

#define DIM   1024
#define NH    16
#define HD    64
#define BATCH 4
#define SEQ   2048
#define SCALE 0.125f   /* 64^{-0.5} */

// Intermediates as __device__ globals (allocation is forbidden).
__device__ float g_qkv[(size_t)BATCH * SEQ * 3 * DIM];   // [B*S, 3*DIM]
__device__ float g_attn[(size_t)BATCH * SEQ * DIM];      // [B*S, DIM]

// ---------------------------------------------------------------------------
// Classic 128x128x8 register-blocked SGEMM.  C[M,N] = A[M,K] @ B[K,N] (+bias)
// 256 threads, each computes an 8x8 micro-tile (2x2 blocks of 4x4).
// ---------------------------------------------------------------------------
template <bool HAS_BIAS>
__global__ __launch_bounds__(256) void sgemm128(
    const float* __restrict__ A, const float* __restrict__ Bm,
    const float* __restrict__ bias, float* __restrict__ C,
    int M, int N, int K)
{
    constexpr int BM = 128, BN = 128, BK = 8;
    __shared__ float As[BK][132];   // padded to dodge STS conflicts; rows 16B aligned
    __shared__ float Bs[BK][BN];

    const int tx = threadIdx.x & 15;   // 0..15
    const int ty = threadIdx.x >> 4;   // 0..15
    const int bRow = blockIdx.y * BM;
    const int bCol = blockIdx.x * BN;

    // A tile load: 128x8 floats, one float4 along K per thread
    const int aRow  = threadIdx.x >> 1;        // 0..127
    const int aCol4 = (threadIdx.x & 1) * 4;   // 0 or 4
    // B tile load: 8x128 floats, one float4 along N per thread
    const int bRowL = threadIdx.x >> 5;        // 0..7
    const int bCol4 = (threadIdx.x & 31) * 4;  // 0..124

    const float* Aptr = A + (size_t)bRow * K;
    const float* Bptr = Bm + bCol;

    float acc[8][8];
#pragma unroll
    for (int i = 0; i < 8; i++)
#pragma unroll
        for (int j = 0; j < 8; j++) acc[i][j] = 0.f;

    for (int k0 = 0; k0 < K; k0 += BK) {
        float4 a4 = *(const float4*)(Aptr + (size_t)aRow * K + k0 + aCol4);
        As[aCol4 + 0][aRow] = a4.x;
        As[aCol4 + 1][aRow] = a4.y;
        As[aCol4 + 2][aRow] = a4.z;
        As[aCol4 + 3][aRow] = a4.w;
        *(float4*)&Bs[bRowL][bCol4] =
            *(const float4*)(Bptr + (size_t)(k0 + bRowL) * N + bCol4);
        __syncthreads();

#pragma unroll
        for (int k = 0; k < BK; k++) {
            float ra[8], rb[8];
            *(float4*)&ra[0] = *(const float4*)&As[k][ty * 4];
            *(float4*)&ra[4] = *(const float4*)&As[k][64 + ty * 4];
            *(float4*)&rb[0] = *(const float4*)&Bs[k][tx * 4];
            *(float4*)&rb[4] = *(const float4*)&Bs[k][64 + tx * 4];
#pragma unroll
            for (int i = 0; i < 8; i++)
#pragma unroll
                for (int j = 0; j < 8; j++)
                    acc[i][j] += ra[i] * rb[j];
        }
        __syncthreads();
    }

    // Epilogue
#pragma unroll
    for (int ih = 0; ih < 2; ih++) {
#pragma unroll
        for (int i = 0; i < 4; i++) {
            int r = bRow + ih * 64 + ty * 4 + i;
            float* Crow = C + (size_t)r * N + bCol;
#pragma unroll
            for (int jh = 0; jh < 2; jh++) {
                int c = jh * 64 + tx * 4;
                float4 v;
                v.x = acc[ih * 4 + i][jh * 4 + 0];
                v.y = acc[ih * 4 + i][jh * 4 + 1];
                v.z = acc[ih * 4 + i][jh * 4 + 2];
                v.w = acc[ih * 4 + i][jh * 4 + 3];
                if (HAS_BIAS) {
                    v.x += bias[bCol + c + 0];
                    v.y += bias[bCol + c + 1];
                    v.z += bias[bCol + c + 2];
                    v.w += bias[bCol + c + 3];
                }
                *(float4*)(Crow + c) = v;
            }
        }
    }
}

// ---------------------------------------------------------------------------
// Flash-style attention, fp32.  One thread owns one query row (q + out accum
// in registers), K/V staged through smem in 64-key tiles.  Online softmax with
// lazy rescale (rescale only when the running max improves).
// Grid: (SEQ/128, NH, BATCH), block: 128 threads.
// ---------------------------------------------------------------------------
__global__ __launch_bounds__(128) void attn_kernel()
{
    const int b = blockIdx.z;
    const int h = blockIdx.y;
    const int s = blockIdx.x * 128 + threadIdx.x;

    const float* base = g_qkv + (size_t)b * SEQ * (3 * DIM);

    float q[HD], o[HD];
    {
        const float4* qp = (const float4*)(base + (size_t)s * (3 * DIM) + h * HD);
#pragma unroll
        for (int i = 0; i < HD / 4; i++) ((float4*)q)[i] = qp[i];
    }
#pragma unroll
    for (int d = 0; d < HD; d++) o[d] = 0.f;

    float m = -1e30f, l = 0.f;

    __shared__ float kS[64 * HD];
    __shared__ float vS[64 * HD];

    for (int j0 = 0; j0 < SEQ; j0 += 64) {
        __syncthreads();
        // Cooperative stage of 64 K rows + 64 V rows (each HD=64 floats).
#pragma unroll
        for (int t = threadIdx.x; t < 64 * (HD / 4); t += 128) {
            int row = t >> 4;        // 0..63
            int c4  = (t & 15) * 4;  // 0..60
            const float* rbase = base + (size_t)(j0 + row) * (3 * DIM) + h * HD;
            *(float4*)&kS[row * HD + c4] = *(const float4*)(rbase + DIM     + c4);
            *(float4*)&vS[row * HD + c4] = *(const float4*)(rbase + 2 * DIM + c4);
        }
        __syncthreads();

#pragma unroll 1
        for (int j = 0; j < 64; j++) {
            const float* krow = &kS[j * HD];
            float a0 = 0.f, a1 = 0.f, a2 = 0.f, a3 = 0.f;
#pragma unroll
            for (int d = 0; d < HD; d += 4) {
                a0 += q[d + 0] * krow[d + 0];
                a1 += q[d + 1] * krow[d + 1];
                a2 += q[d + 2] * krow[d + 2];
                a3 += q[d + 3] * krow[d + 3];
            }
            float sc = ((a0 + a1) + (a2 + a3)) * SCALE;

            if (sc > m) {                      // rare after warm-up
                float corr = __expf(m - sc);
                l *= corr;
#pragma unroll
                for (int d = 0; d < HD; d++) o[d] *= corr;
                m = sc;
            }
            float p = __expf(sc - m);
            l += p;

            const float* vrow = &vS[j * HD];
#pragma unroll
            for (int d = 0; d < HD; d++) o[d] += p * vrow[d];
        }
    }

    float inv = 1.f / l;
    float* op = g_attn + ((size_t)b * SEQ + s) * DIM + h * HD;
#pragma unroll
    for (int i = 0; i < HD / 4; i++) {
        float4 v;
        v.x = o[i * 4 + 0] * inv;
        v.y = o[i * 4 + 1] * inv;
        v.z = o[i * 4 + 2] * inv;
        v.w = o[i * 4 + 3] * inv;
        *(float4*)(op + i * 4) = v;
    }
}

// ---------------------------------------------------------------------------
extern "C" void kernel_launch(void* const* d_in, const int* in_sizes, int n_in,
                              void* d_out, int out_size)
{
    const float* x     = (const float*)d_in[0];
    const float* w_qkv = (const float*)d_in[1];
    const float* w_out = (const float*)d_in[2];
    const float* b_out = (const float*)d_in[3];
    float*       out   = (float*)d_out;

    float *qkv, *attn;
    cudaGetSymbolAddress((void**)&qkv,  g_qkv);
    cudaGetSymbolAddress((void**)&attn, g_attn);

    const int M = BATCH * SEQ;  // 8192

    // 1) QKV projection: [8192,1024] @ [1024,3072]
    {
        dim3 grid(3 * DIM / 128, M / 128);
        sgemm128<false><<<grid, 256>>>(x, w_qkv, nullptr, qkv, M, 3 * DIM, DIM);
    }
    // 2) Attention
    {
        dim3 grid(SEQ / 128, NH, BATCH);
        attn_kernel<<<grid, 128>>>();
    }
    // 3) Output projection + bias: [8192,1024] @ [1024,1024] + b
    {
        dim3 grid(DIM / 128, M / 128);
        sgemm128<true><<<grid, 256>>>(attn, w_out, b_out, out, M, DIM, DIM);
    }
}

// round 4
// speedup vs baseline: 1.2988x; 1.2988x over previous
#include <cuda_runtime.h>
#include <cstdint>
#include <math.h>

#define DIM   1024
#define NH    16
#define HD    64
#define BATCH 4
#define SEQ   2048
#define SCALE 0.125f

typedef unsigned long long u64;

__device__ float g_qkv[(size_t)BATCH * SEQ * 3 * DIM];   // [B*S, 3*DIM]
__device__ float g_attn[(size_t)BATCH * SEQ * DIM];      // [B*S, DIM]

// ---------------------------------------------------------------------------
// helpers
// ---------------------------------------------------------------------------
__device__ __forceinline__ uint32_t smem_u32(const void* p) {
    uint32_t a;
    asm("{ .reg .u64 t; cvta.to.shared.u64 t, %1; cvt.u32.u64 %0, t; }"
        : "=r"(a) : "l"(p));
    return a;
}
__device__ __forceinline__ void ldsm4(uint32_t (&r)[4], uint32_t addr) {
    asm volatile("ldmatrix.sync.aligned.m8n8.x4.shared.b16 {%0,%1,%2,%3}, [%4];"
                 : "=r"(r[0]), "=r"(r[1]), "=r"(r[2]), "=r"(r[3]) : "r"(addr));
}
__device__ __forceinline__ void mma_tf32(float (&c)[4], const uint32_t a[4],
                                         const uint32_t b0, const uint32_t b1) {
    asm volatile(
        "mma.sync.aligned.m16n8k8.row.col.f32.tf32.tf32.f32 "
        "{%0,%1,%2,%3}, {%4,%5,%6,%7}, {%8,%9}, {%0,%1,%2,%3};"
        : "+f"(c[0]), "+f"(c[1]), "+f"(c[2]), "+f"(c[3])
        : "r"(a[0]), "r"(a[1]), "r"(a[2]), "r"(a[3]), "r"(b0), "r"(b1));
}
__device__ __forceinline__ uint32_t f2tf32(float x) {
    uint32_t u;
    asm("cvt.rna.tf32.f32 %0, %1;" : "=r"(u) : "f"(x));
    return u;
}

// packed f32x2 helpers
__device__ __forceinline__ u64 fma2(u64 a, u64 b, u64 c) {
    u64 d; asm("fma.rn.f32x2 %0, %1, %2, %3;" : "=l"(d) : "l"(a), "l"(b), "l"(c)); return d;
}
__device__ __forceinline__ u64 mul2(u64 a, u64 b) {
    u64 d; asm("mul.rn.f32x2 %0, %1, %2;" : "=l"(d) : "l"(a), "l"(b)); return d;
}
__device__ __forceinline__ u64 pack2(float lo, float hi) {
    u64 d; asm("mov.b64 %0, {%1, %2};" : "=l"(d) : "f"(lo), "f"(hi)); return d;
}
__device__ __forceinline__ void unpack2(float& lo, float& hi, u64 v) {
    asm("mov.b64 {%0, %1}, %2;" : "=f"(lo), "=f"(hi) : "l"(v));
}

// ---------------------------------------------------------------------------
// tf32 mma.sync GEMM: C[M,N] = A[M,K] @ B[K,N] (+bias)
// 128x128 CTA tile, BK=32, 8 warps (2m x 4n -> 64x32 warp tiles),
// double-buffered smem with 16B XOR swizzle, ldmatrix.x4 fragments.
// All staged data is cvt.rna.tf32 rounded (unbiased).
// Smem element layouts (float index, per buffer of 128x32):
//   A[row][k] -> row*32 + 4*((k/4) ^ (row&7)) + k%4   (row-major, k quads swizzled)
//   B[n][k]   -> n*32   + 4*((k/4) ^ (n&7))   + k%4   (n-major for .col operand)
// ---------------------------------------------------------------------------
static constexpr int GEMM_SMEM = 4 * 16384;   // A0,A1,B0,B1

template <bool HAS_BIAS>
__global__ __launch_bounds__(256)
void gemm_tf32(const float* __restrict__ A, const float* __restrict__ B,
               const float* __restrict__ bias, float* __restrict__ C,
               int M, int N, int K)
{
    extern __shared__ float smem[];
    float* Abuf[2] = { smem,            smem + 4096 };
    float* Bbuf[2] = { smem + 8192,     smem + 12288 };
    const uint32_t sb = smem_u32(smem);
    const uint32_t Au[2] = { sb,           sb + 16384 };
    const uint32_t Bu[2] = { sb + 32768,   sb + 49152 };

    const int tid  = threadIdx.x;
    const int wid  = tid >> 5;
    const int lane = tid & 31;
    const int wm   = wid >> 2;       // 0..1
    const int wn   = wid & 3;        // 0..3
    const int bRow = blockIdx.y * 128;
    const int bCol = blockIdx.x * 128;

    // staging maps
    const int aRow = tid >> 1;            // 0..127
    const int aQ0  = (tid & 1) * 4;       // quad 0..3 or 4..7
    const int bN   = tid & 127;
    const int bKq  = tid >> 7;            // 0..1 (+2*s)

    const float* Ap = A + (size_t)bRow * K;
    const float* Bp = B + bCol;

    // ldmatrix lane mappings.
    // A fragment (a1 = row+8):  matrix1 -> rows+8 (lane>>3), matrix2 -> k-hi (lane>>4)
    // B fragment (b1 = k+4):    matrix1 -> k-hi (lane>>3),   matrix2 -> n+8  (lane>>4)
    const int r8    = lane & 7;
    const int hselA = (lane >> 3) & 1;
    const int gselA = (lane >> 4) & 1;
    const int gselB = (lane >> 3) & 1;
    const int hselB = (lane >> 4) & 1;
    const int rowA  = wm * 64 + hselA * 8 + r8;
    const int rowB0 = wn * 32 + hselB * 8 + r8;

    float acc[4][4][4];
#pragma unroll
    for (int i = 0; i < 4; i++)
#pragma unroll
        for (int j = 0; j < 4; j++)
#pragma unroll
            for (int v = 0; v < 4; v++) acc[i][j][v] = 0.f;

    float4 apre[4];
    float  bpre[4][4];

    auto ldgA = [&](int kc) {
#pragma unroll
        for (int i = 0; i < 4; i++)
            apre[i] = *(const float4*)(Ap + (size_t)aRow * K + kc * 32 + (aQ0 + i) * 4);
    };
    auto stsA = [&](int buf) {
#pragma unroll
        for (int i = 0; i < 4; i++) {
            uint4 w = { f2tf32(apre[i].x), f2tf32(apre[i].y),
                        f2tf32(apre[i].z), f2tf32(apre[i].w) };
            *(uint4*)&Abuf[buf][aRow * 32 + 4 * ((aQ0 + i) ^ (aRow & 7))] = w;
        }
    };
    auto ldgB = [&](int kc) {
#pragma unroll
        for (int s = 0; s < 4; s++) {
            int kq = s * 2 + bKq;
#pragma unroll
            for (int j = 0; j < 4; j++)
                bpre[s][j] = Bp[(size_t)(kc * 32 + kq * 4 + j) * N + bN];
        }
    };
    auto stsB = [&](int buf) {
#pragma unroll
        for (int s = 0; s < 4; s++) {
            int kq = s * 2 + bKq;
            uint4 w = { f2tf32(bpre[s][0]), f2tf32(bpre[s][1]),
                        f2tf32(bpre[s][2]), f2tf32(bpre[s][3]) };
            *(uint4*)&Bbuf[buf][bN * 32 + 4 * (kq ^ (bN & 7))] = w;
        }
    };

    const int NC = K / 32;

    ldgA(0); ldgB(0);
    stsA(0); stsB(0);
    __syncthreads();

#pragma unroll 1
    for (int kc = 0; kc < NC; kc++) {
        const int buf = kc & 1;
        if (kc + 1 < NC) { ldgA(kc + 1); ldgB(kc + 1); }

        const uint32_t aB = Au[buf];
        const uint32_t bB = Bu[buf];
#pragma unroll
        for (int ks = 0; ks < 4; ks++) {
            const int qA = 2 * ks + gselA;
            const int qB = 2 * ks + gselB;
            uint32_t breg[2][4];
#pragma unroll
            for (int np = 0; np < 2; np++) {
                int row = rowB0 + np * 16;
                ldsm4(breg[np], bB + (uint32_t)(row * 32 + 4 * (qB ^ r8)) * 4u);
            }
#pragma unroll
            for (int mi = 0; mi < 4; mi++) {
                uint32_t areg[4];
                int row = rowA + mi * 16;
                ldsm4(areg, aB + (uint32_t)(row * 32 + 4 * (qA ^ r8)) * 4u);
#pragma unroll
                for (int ni = 0; ni < 4; ni++) {
                    const uint32_t* br = breg[ni >> 1];
                    int off = (ni & 1) * 2;
                    mma_tf32(acc[mi][ni], areg, br[off], br[off + 1]);
                }
            }
        }

        if (kc + 1 < NC) {
            __syncthreads();       // all reads of buf^1 from previous chunk done
            stsA(buf ^ 1);
            stsB(buf ^ 1);
            __syncthreads();
        }
    }

    // epilogue: direct float2 stores
    const int erow = lane >> 2;
    const int ecol = (lane & 3) * 2;
#pragma unroll
    for (int mi = 0; mi < 4; mi++) {
#pragma unroll
        for (int ni = 0; ni < 4; ni++) {
            int col = bCol + wn * 32 + ni * 8 + ecol;
            float bx = 0.f, by = 0.f;
            if (HAS_BIAS) { bx = bias[col]; by = bias[col + 1]; }
            int r0 = bRow + wm * 64 + mi * 16 + erow;
            float2 v0 = { acc[mi][ni][0] + bx, acc[mi][ni][1] + by };
            float2 v1 = { acc[mi][ni][2] + bx, acc[mi][ni][3] + by };
            *(float2*)(C + (size_t)r0 * N + col) = v0;
            *(float2*)(C + (size_t)(r0 + 8) * N + col) = v1;
        }
    }
}

// ---------------------------------------------------------------------------
// Flash attention, packed f32x2 FMA.  One thread per query row.
// ---------------------------------------------------------------------------
__global__ __launch_bounds__(128) void attn_kernel()
{
    const int b = blockIdx.z;
    const int h = blockIdx.y;
    const int s = blockIdx.x * 128 + threadIdx.x;

    const float* base = g_qkv + (size_t)b * SEQ * (3 * DIM);

    u64 q2[32], o2[32];
    {
        const ulonglong2* qp =
            (const ulonglong2*)(base + (size_t)s * (3 * DIM) + h * HD);
#pragma unroll
        for (int i = 0; i < 16; i++) {
            ulonglong2 t = qp[i];
            q2[2 * i] = t.x; q2[2 * i + 1] = t.y;
        }
    }
#pragma unroll
    for (int i = 0; i < 32; i++) o2[i] = 0ull;

    float m = -1e30f, l = 0.f;

    __shared__ __align__(16) float kS[64 * HD];
    __shared__ __align__(16) float vS[64 * HD];

    for (int j0 = 0; j0 < SEQ; j0 += 64) {
        __syncthreads();
#pragma unroll
        for (int t = threadIdx.x; t < 64 * (HD / 4); t += 128) {
            int row = t >> 4;
            int c4  = (t & 15) * 4;
            const float* rb = base + (size_t)(j0 + row) * (3 * DIM) + h * HD;
            *(float4*)&kS[row * HD + c4] = *(const float4*)(rb + DIM     + c4);
            *(float4*)&vS[row * HD + c4] = *(const float4*)(rb + 2 * DIM + c4);
        }
        __syncthreads();

#pragma unroll 1
        for (int j = 0; j < 64; j++) {
            const ulonglong2* k2 = (const ulonglong2*)&kS[j * HD];
            u64 a0 = 0, a1 = 0, a2 = 0, a3 = 0;
#pragma unroll
            for (int i = 0; i < 8; i++) {
                ulonglong2 kA = k2[2 * i];
                ulonglong2 kB = k2[2 * i + 1];
                a0 = fma2(q2[4 * i + 0], kA.x, a0);
                a1 = fma2(q2[4 * i + 1], kA.y, a1);
                a2 = fma2(q2[4 * i + 2], kB.x, a2);
                a3 = fma2(q2[4 * i + 3], kB.y, a3);
            }
            float x0, x1, x2, x3, x4, x5, x6, x7;
            unpack2(x0, x1, a0); unpack2(x2, x3, a1);
            unpack2(x4, x5, a2); unpack2(x6, x7, a3);
            float sc = (((x0 + x1) + (x2 + x3)) + ((x4 + x5) + (x6 + x7))) * SCALE;

            if (sc > m) {
                float corr = __expf(m - sc);
                l *= corr;
                u64 c2 = pack2(corr, corr);
#pragma unroll
                for (int i = 0; i < 32; i++) o2[i] = mul2(o2[i], c2);
                m = sc;
            }
            float p = __expf(sc - m);
            l += p;
            u64 p2 = pack2(p, p);

            const ulonglong2* v2 = (const ulonglong2*)&vS[j * HD];
#pragma unroll
            for (int i = 0; i < 16; i++) {
                ulonglong2 vv = v2[i];
                o2[2 * i]     = fma2(p2, vv.x, o2[2 * i]);
                o2[2 * i + 1] = fma2(p2, vv.y, o2[2 * i + 1]);
            }
        }
    }

    float inv = 1.f / l;
    u64 inv2 = pack2(inv, inv);
    ulonglong2* op = (ulonglong2*)(g_attn + ((size_t)b * SEQ + s) * DIM + h * HD);
#pragma unroll
    for (int i = 0; i < 16; i++) {
        ulonglong2 t;
        t.x = mul2(o2[2 * i], inv2);
        t.y = mul2(o2[2 * i + 1], inv2);
        op[i] = t;
    }
}

// ---------------------------------------------------------------------------
extern "C" void kernel_launch(void* const* d_in, const int* in_sizes, int n_in,
                              void* d_out, int out_size)
{
    const float* x     = (const float*)d_in[0];
    const float* w_qkv = (const float*)d_in[1];
    const float* w_out = (const float*)d_in[2];
    const float* b_out = (const float*)d_in[3];
    float*       out   = (float*)d_out;

    float *qkv, *attn;
    cudaGetSymbolAddress((void**)&qkv,  g_qkv);
    cudaGetSymbolAddress((void**)&attn, g_attn);

    cudaFuncSetAttribute(gemm_tf32<false>,
                         cudaFuncAttributeMaxDynamicSharedMemorySize, GEMM_SMEM);
    cudaFuncSetAttribute(gemm_tf32<true>,
                         cudaFuncAttributeMaxDynamicSharedMemorySize, GEMM_SMEM);

    const int M = BATCH * SEQ;  // 8192

    gemm_tf32<false><<<dim3(3 * DIM / 128, M / 128), 256, GEMM_SMEM>>>(
        x, w_qkv, nullptr, qkv, M, 3 * DIM, DIM);

    attn_kernel<<<dim3(SEQ / 128, NH, BATCH), 128>>>();

    gemm_tf32<true><<<dim3(DIM / 128, M / 128), 256, GEMM_SMEM>>>(
        attn, w_out, b_out, out, M, DIM, DIM);
}

// round 5
// speedup vs baseline: 3.3777x; 2.6007x over previous
#include <cuda_runtime.h>
#include <cstdint>
#include <math.h>

#define DIM   1024
#define NH    16
#define HD    64
#define BATCH 4
#define SEQ   2048
#define SCALE 0.125f
#define CSC   0.18033688011112042f   /* SCALE * log2(e) */

typedef unsigned long long u64;

__device__ float g_qkv[(size_t)BATCH * SEQ * 3 * DIM];   // [B*S, 3*DIM]
__device__ float g_attn[(size_t)BATCH * SEQ * DIM];      // [B*S, DIM]

// ---------------------------------------------------------------------------
// helpers
// ---------------------------------------------------------------------------
__device__ __forceinline__ uint32_t smem_u32(const void* p) {
    uint32_t a;
    asm("{ .reg .u64 t; cvta.to.shared.u64 t, %1; cvt.u32.u64 %0, t; }"
        : "=r"(a) : "l"(p));
    return a;
}
__device__ __forceinline__ void ldsm4(uint32_t (&r)[4], uint32_t addr) {
    asm volatile("ldmatrix.sync.aligned.m8n8.x4.shared.b16 {%0,%1,%2,%3}, [%4];"
                 : "=r"(r[0]), "=r"(r[1]), "=r"(r[2]), "=r"(r[3]) : "r"(addr));
}
__device__ __forceinline__ void ldsm4p(uint32_t* r, uint32_t addr) {
    asm volatile("ldmatrix.sync.aligned.m8n8.x4.shared.b16 {%0,%1,%2,%3}, [%4];"
                 : "=r"(r[0]), "=r"(r[1]), "=r"(r[2]), "=r"(r[3]) : "r"(addr));
}
__device__ __forceinline__ void ldsm4t(uint32_t* r, uint32_t addr) {
    asm volatile("ldmatrix.sync.aligned.m8n8.x4.trans.shared.b16 {%0,%1,%2,%3}, [%4];"
                 : "=r"(r[0]), "=r"(r[1]), "=r"(r[2]), "=r"(r[3]) : "r"(addr));
}
__device__ __forceinline__ void mma_tf32(float (&c)[4], const uint32_t a[4],
                                         const uint32_t b0, const uint32_t b1) {
    asm volatile(
        "mma.sync.aligned.m16n8k8.row.col.f32.tf32.tf32.f32 "
        "{%0,%1,%2,%3}, {%4,%5,%6,%7}, {%8,%9}, {%0,%1,%2,%3};"
        : "+f"(c[0]), "+f"(c[1]), "+f"(c[2]), "+f"(c[3])
        : "r"(a[0]), "r"(a[1]), "r"(a[2]), "r"(a[3]), "r"(b0), "r"(b1));
}
__device__ __forceinline__ void mma_f16(float (&c)[4],
                                        uint32_t a0, uint32_t a1, uint32_t a2, uint32_t a3,
                                        uint32_t b0, uint32_t b1) {
    asm volatile(
        "mma.sync.aligned.m16n8k16.row.col.f32.f16.f16.f32 "
        "{%0,%1,%2,%3}, {%4,%5,%6,%7}, {%8,%9}, {%0,%1,%2,%3};"
        : "+f"(c[0]), "+f"(c[1]), "+f"(c[2]), "+f"(c[3])
        : "r"(a0), "r"(a1), "r"(a2), "r"(a3), "r"(b0), "r"(b1));
}
__device__ __forceinline__ uint32_t f2tf32(float x) {
    uint32_t u;
    asm("cvt.rna.tf32.f32 %0, %1;" : "=r"(u) : "f"(x));
    return u;
}
__device__ __forceinline__ uint32_t cvt16x2(float hi, float lo) {
    uint32_t d;
    asm("cvt.rn.f16x2.f32 %0, %1, %2;" : "=r"(d) : "f"(hi), "f"(lo));
    return d;
}
__device__ __forceinline__ float ex2f(float x) {
    float r;
    asm("ex2.approx.ftz.f32 %0, %1;" : "=f"(r) : "f"(x));
    return r;
}

// ---------------------------------------------------------------------------
// tf32 mma.sync GEMM (unchanged from R4): C = A @ B (+bias), 128x128x32 tiles.
// ---------------------------------------------------------------------------
static constexpr int GEMM_SMEM = 4 * 16384;

template <bool HAS_BIAS>
__global__ __launch_bounds__(256)
void gemm_tf32(const float* __restrict__ A, const float* __restrict__ B,
               const float* __restrict__ bias, float* __restrict__ C,
               int M, int N, int K)
{
    extern __shared__ float smem[];
    float* Abuf[2] = { smem,            smem + 4096 };
    float* Bbuf[2] = { smem + 8192,     smem + 12288 };
    const uint32_t sb = smem_u32(smem);
    const uint32_t Au[2] = { sb,           sb + 16384 };
    const uint32_t Bu[2] = { sb + 32768,   sb + 49152 };

    const int tid  = threadIdx.x;
    const int wid  = tid >> 5;
    const int lane = tid & 31;
    const int wm   = wid >> 2;
    const int wn   = wid & 3;
    const int bRow = blockIdx.y * 128;
    const int bCol = blockIdx.x * 128;

    const int aRow = tid >> 1;
    const int aQ0  = (tid & 1) * 4;
    const int bN   = tid & 127;
    const int bKq  = tid >> 7;

    const float* Ap = A + (size_t)bRow * K;
    const float* Bp = B + bCol;

    const int r8    = lane & 7;
    const int hselA = (lane >> 3) & 1;
    const int gselA = (lane >> 4) & 1;
    const int gselB = (lane >> 3) & 1;
    const int hselB = (lane >> 4) & 1;
    const int rowA  = wm * 64 + hselA * 8 + r8;
    const int rowB0 = wn * 32 + hselB * 8 + r8;

    float acc[4][4][4];
#pragma unroll
    for (int i = 0; i < 4; i++)
#pragma unroll
        for (int j = 0; j < 4; j++)
#pragma unroll
            for (int v = 0; v < 4; v++) acc[i][j][v] = 0.f;

    float4 apre[4];
    float  bpre[4][4];

    auto ldgA = [&](int kc) {
#pragma unroll
        for (int i = 0; i < 4; i++)
            apre[i] = *(const float4*)(Ap + (size_t)aRow * K + kc * 32 + (aQ0 + i) * 4);
    };
    auto stsA = [&](int buf) {
#pragma unroll
        for (int i = 0; i < 4; i++) {
            uint4 w = { f2tf32(apre[i].x), f2tf32(apre[i].y),
                        f2tf32(apre[i].z), f2tf32(apre[i].w) };
            *(uint4*)&Abuf[buf][aRow * 32 + 4 * ((aQ0 + i) ^ (aRow & 7))] = w;
        }
    };
    auto ldgB = [&](int kc) {
#pragma unroll
        for (int s = 0; s < 4; s++) {
            int kq = s * 2 + bKq;
#pragma unroll
            for (int j = 0; j < 4; j++)
                bpre[s][j] = Bp[(size_t)(kc * 32 + kq * 4 + j) * N + bN];
        }
    };
    auto stsB = [&](int buf) {
#pragma unroll
        for (int s = 0; s < 4; s++) {
            int kq = s * 2 + bKq;
            uint4 w = { f2tf32(bpre[s][0]), f2tf32(bpre[s][1]),
                        f2tf32(bpre[s][2]), f2tf32(bpre[s][3]) };
            *(uint4*)&Bbuf[buf][bN * 32 + 4 * (kq ^ (bN & 7))] = w;
        }
    };

    const int NC = K / 32;

    ldgA(0); ldgB(0);
    stsA(0); stsB(0);
    __syncthreads();

#pragma unroll 1
    for (int kc = 0; kc < NC; kc++) {
        const int buf = kc & 1;
        if (kc + 1 < NC) { ldgA(kc + 1); ldgB(kc + 1); }

        const uint32_t aB = Au[buf];
        const uint32_t bB = Bu[buf];
#pragma unroll
        for (int ks = 0; ks < 4; ks++) {
            const int qA = 2 * ks + gselA;
            const int qB = 2 * ks + gselB;
            uint32_t breg[2][4];
#pragma unroll
            for (int np = 0; np < 2; np++) {
                int row = rowB0 + np * 16;
                ldsm4(breg[np], bB + (uint32_t)(row * 32 + 4 * (qB ^ r8)) * 4u);
            }
#pragma unroll
            for (int mi = 0; mi < 4; mi++) {
                uint32_t areg[4];
                int row = rowA + mi * 16;
                ldsm4(areg, aB + (uint32_t)(row * 32 + 4 * (qA ^ r8)) * 4u);
#pragma unroll
                for (int ni = 0; ni < 4; ni++) {
                    const uint32_t* br = breg[ni >> 1];
                    int off = (ni & 1) * 2;
                    mma_tf32(acc[mi][ni], areg, br[off], br[off + 1]);
                }
            }
        }

        if (kc + 1 < NC) {
            __syncthreads();
            stsA(buf ^ 1);
            stsB(buf ^ 1);
            __syncthreads();
        }
    }

    const int erow = lane >> 2;
    const int ecol = (lane & 3) * 2;
#pragma unroll
    for (int mi = 0; mi < 4; mi++) {
#pragma unroll
        for (int ni = 0; ni < 4; ni++) {
            int col = bCol + wn * 32 + ni * 8 + ecol;
            float bx = 0.f, by = 0.f;
            if (HAS_BIAS) { bx = bias[col]; by = bias[col + 1]; }
            int r0 = bRow + wm * 64 + mi * 16 + erow;
            float2 v0 = { acc[mi][ni][0] + bx, acc[mi][ni][1] + by };
            float2 v1 = { acc[mi][ni][2] + bx, acc[mi][ni][3] + by };
            *(float2*)(C + (size_t)r0 * N + col) = v0;
            *(float2*)(C + (size_t)(r0 + 8) * N + col) = v1;
        }
    }
}

// ---------------------------------------------------------------------------
// Tensor-core flash attention (fp16 mma, f32 accum, fp32 exp).
// CTA: 256 threads = 8 warps; 128 query rows (16/warp); 64-key tiles.
// K/V smem: [64 rows][64 fp16], 16B chunks XOR-swizzled: chunk c -> c^(r&7).
// l accumulated by mma against constant-ones B fragment.
// ---------------------------------------------------------------------------
__global__ __launch_bounds__(256) void attn_fa()
{
    const int b    = blockIdx.z;
    const int h    = blockIdx.y;
    const int tid  = threadIdx.x;
    const int warp = tid >> 5;
    const int lane = tid & 31;

    __shared__ __align__(16) uint32_t kS[64 * 32];   // 8KB
    __shared__ __align__(16) uint32_t vS[64 * 32];   // 8KB
    const uint32_t kBase = smem_u32(kS);
    const uint32_t vBase = smem_u32(vS);

    const float* qkvB = g_qkv + (size_t)b * SEQ * (3 * DIM);

    // ---- Q fragments (fp16), rows warp*16 + lane/4 (+8) ----
    const int rloc    = warp * 16 + (lane >> 2);
    const int grow_lo = blockIdx.x * 128 + rloc;
    const float* qp_lo = qkvB + (size_t)grow_lo * (3 * DIM) + h * HD;
    const float* qp_hi = qp_lo + (size_t)8 * (3 * DIM);

    uint32_t qf[4][4];
#pragma unroll
    for (int j = 0; j < 4; j++) {
        int k0 = j * 16 + 2 * (lane & 3);
        float2 v;
        v = *(const float2*)(qp_lo + k0);     qf[j][0] = cvt16x2(v.y, v.x);
        v = *(const float2*)(qp_hi + k0);     qf[j][1] = cvt16x2(v.y, v.x);
        v = *(const float2*)(qp_lo + k0 + 8); qf[j][2] = cvt16x2(v.y, v.x);
        v = *(const float2*)(qp_hi + k0 + 8); qf[j][3] = cvt16x2(v.y, v.x);
    }

    float O[8][4];
#pragma unroll
    for (int i = 0; i < 8; i++)
#pragma unroll
        for (int c = 0; c < 4; c++) O[i][c] = 0.f;
    float lacc[4] = { 0.f, 0.f, 0.f, 0.f };
    float m_lo = -1e30f, m_hi = -1e30f;

    // staging map: thread t -> row t/4, col-group t%4 (16 floats)
    const int sr  = tid >> 2;
    const int scq = tid & 3;
    const uint32_t ONES = 0x3C003C00u;

#pragma unroll 1
    for (int j0 = 0; j0 < SEQ; j0 += 64) {
        __syncthreads();
        {
            const float* kr = qkvB + (size_t)(j0 + sr) * (3 * DIM) + DIM + h * HD;
            const float* vr = kr + DIM;
#pragma unroll
            for (int i = 0; i < 8; i++) {
                int c = scq * 16 + 2 * i;
                uint32_t off = (uint32_t)sr * 32 + 4 * ((c >> 3) ^ (sr & 7)) + ((c >> 1) & 3);
                float2 a = *(const float2*)(kr + c);
                kS[off] = cvt16x2(a.y, a.x);
                float2 w = *(const float2*)(vr + c);
                vS[off] = cvt16x2(w.y, w.x);
            }
        }
        __syncthreads();

        // ---- S = Q K^T  (16 x 64 per warp) ----
        float S[8][4];
#pragma unroll
        for (int nt = 0; nt < 8; nt++)
#pragma unroll
            for (int c = 0; c < 4; c++) S[nt][c] = 0.f;

#pragma unroll
        for (int nt = 0; nt < 8; nt++) {
            uint32_t bk[8];
#pragma unroll
            for (int ks2 = 0; ks2 < 2; ks2++) {
                int mrow  = 8 * nt + (lane & 7);
                int chunk = ks2 * 4 + (lane >> 3);
                ldsm4p(&bk[ks2 * 4],
                       kBase + (uint32_t)(mrow * 32 + 4 * (chunk ^ (mrow & 7))) * 4u);
            }
            mma_f16(S[nt], qf[0][0], qf[0][1], qf[0][2], qf[0][3], bk[0], bk[1]);
            mma_f16(S[nt], qf[1][0], qf[1][1], qf[1][2], qf[1][3], bk[2], bk[3]);
            mma_f16(S[nt], qf[2][0], qf[2][1], qf[2][2], qf[2][3], bk[4], bk[5]);
            mma_f16(S[nt], qf[3][0], qf[3][1], qf[3][2], qf[3][3], bk[6], bk[7]);
        }

        // ---- online softmax (base-2) ----
        float tmax_lo = -1e30f, tmax_hi = -1e30f;
#pragma unroll
        for (int nt = 0; nt < 8; nt++) {
            S[nt][0] *= CSC; S[nt][1] *= CSC; S[nt][2] *= CSC; S[nt][3] *= CSC;
            tmax_lo = fmaxf(tmax_lo, fmaxf(S[nt][0], S[nt][1]));
            tmax_hi = fmaxf(tmax_hi, fmaxf(S[nt][2], S[nt][3]));
        }
        tmax_lo = fmaxf(tmax_lo, __shfl_xor_sync(0xffffffffu, tmax_lo, 1));
        tmax_lo = fmaxf(tmax_lo, __shfl_xor_sync(0xffffffffu, tmax_lo, 2));
        tmax_hi = fmaxf(tmax_hi, __shfl_xor_sync(0xffffffffu, tmax_hi, 1));
        tmax_hi = fmaxf(tmax_hi, __shfl_xor_sync(0xffffffffu, tmax_hi, 2));

        const float mn_lo = fmaxf(m_lo, tmax_lo);
        const float mn_hi = fmaxf(m_hi, tmax_hi);
        const float al = ex2f(m_lo - mn_lo);
        const float ah = ex2f(m_hi - mn_hi);
        m_lo = mn_lo; m_hi = mn_hi;

#pragma unroll
        for (int nt = 0; nt < 8; nt++) {
            O[nt][0] *= al; O[nt][1] *= al; O[nt][2] *= ah; O[nt][3] *= ah;
        }
        lacc[0] *= al; lacc[1] *= al; lacc[2] *= ah; lacc[3] *= ah;

        uint32_t P[8][2];
#pragma unroll
        for (int nt = 0; nt < 8; nt++) {
            float p0 = ex2f(S[nt][0] - mn_lo);
            float p1 = ex2f(S[nt][1] - mn_lo);
            float p2 = ex2f(S[nt][2] - mn_hi);
            float p3 = ex2f(S[nt][3] - mn_hi);
            P[nt][0] = cvt16x2(p1, p0);
            P[nt][1] = cvt16x2(p3, p2);
        }

        // l += P @ ones
#pragma unroll
        for (int ks = 0; ks < 4; ks++)
            mma_f16(lacc, P[2 * ks][0], P[2 * ks][1], P[2 * ks + 1][0], P[2 * ks + 1][1],
                    ONES, ONES);

        // ---- O += P @ V ----
#pragma unroll
        for (int nt = 0; nt < 8; nt++) {
            uint32_t bv[8];
#pragma unroll
            for (int kp = 0; kp < 2; kp++) {
                int mrow = 32 * kp + 8 * (lane >> 3) + (lane & 7);
                ldsm4t(&bv[kp * 4],
                       vBase + (uint32_t)(mrow * 32 + 4 * (nt ^ (mrow & 7))) * 4u);
            }
#pragma unroll
            for (int ks = 0; ks < 4; ks++)
                mma_f16(O[nt], P[2 * ks][0], P[2 * ks][1], P[2 * ks + 1][0], P[2 * ks + 1][1],
                        bv[2 * ks], bv[2 * ks + 1]);
        }
    }

    // ---- finalize: O / l, write f32 ----
    const float inv_lo = 1.f / lacc[0];
    const float inv_hi = 1.f / lacc[2];
    float* orow_lo = g_attn + ((size_t)(b * SEQ) + grow_lo) * DIM + h * HD;
    float* orow_hi = orow_lo + (size_t)8 * DIM;
#pragma unroll
    for (int nt = 0; nt < 8; nt++) {
        int col = nt * 8 + 2 * (lane & 3);
        float2 vlo = { O[nt][0] * inv_lo, O[nt][1] * inv_lo };
        float2 vhi = { O[nt][2] * inv_hi, O[nt][3] * inv_hi };
        *(float2*)(orow_lo + col) = vlo;
        *(float2*)(orow_hi + col) = vhi;
    }
}

// ---------------------------------------------------------------------------
extern "C" void kernel_launch(void* const* d_in, const int* in_sizes, int n_in,
                              void* d_out, int out_size)
{
    const float* x     = (const float*)d_in[0];
    const float* w_qkv = (const float*)d_in[1];
    const float* w_out = (const float*)d_in[2];
    const float* b_out = (const float*)d_in[3];
    float*       out   = (float*)d_out;

    float *qkv, *attn;
    cudaGetSymbolAddress((void**)&qkv,  g_qkv);
    cudaGetSymbolAddress((void**)&attn, g_attn);

    cudaFuncSetAttribute(gemm_tf32<false>,
                         cudaFuncAttributeMaxDynamicSharedMemorySize, GEMM_SMEM);
    cudaFuncSetAttribute(gemm_tf32<true>,
                         cudaFuncAttributeMaxDynamicSharedMemorySize, GEMM_SMEM);

    const int M = BATCH * SEQ;  // 8192

    gemm_tf32<false><<<dim3(3 * DIM / 128, M / 128), 256, GEMM_SMEM>>>(
        x, w_qkv, nullptr, qkv, M, 3 * DIM, DIM);

    attn_fa<<<dim3(SEQ / 128, NH, BATCH), 256>>>();

    gemm_tf32<true><<<dim3(DIM / 128, M / 128), 256, GEMM_SMEM>>>(
        attn, w_out, b_out, out, M, DIM, DIM);
}

// round 6
// speedup vs baseline: 8.0453x; 2.3819x over previous
#include <cuda_runtime.h>
#include <cuda_fp16.h>
#include <cstdint>
#include <math.h>

#define DIM   1024
#define NH    16
#define HD    64
#define BATCH 4
#define SEQ   2048
#define CSC   0.18033688011112042f   /* 64^-0.5 * log2(e) */

#define MROWS (BATCH * SEQ)          /* 8192 */

// fp16 staging buffers (allocation is forbidden -> __device__ globals)
__device__ __half g_x_h   [(size_t)MROWS * DIM];
__device__ __half g_wqkv_h[(size_t)3 * DIM * DIM];    // [3*DIM][DIM] = [N][K]
__device__ __half g_wout_h[(size_t)DIM * DIM];        // [N][K]
__device__ __half g_qkv_h [(size_t)MROWS * 3 * DIM];
__device__ __half g_attn_h[(size_t)MROWS * DIM];

// ---------------------------------------------------------------------------
// helpers
// ---------------------------------------------------------------------------
__device__ __forceinline__ uint32_t smem_u32(const void* p) {
    uint32_t a;
    asm("{ .reg .u64 t; cvta.to.shared.u64 t, %1; cvt.u32.u64 %0, t; }"
        : "=r"(a) : "l"(p));
    return a;
}
__device__ __forceinline__ void cp_async16(uint32_t dst, const void* src) {
    asm volatile("cp.async.cg.shared.global [%0], [%1], 16;"
                 :: "r"(dst), "l"(src) : "memory");
}
__device__ __forceinline__ void cp_commit() {
    asm volatile("cp.async.commit_group;" ::: "memory");
}
template <int N>
__device__ __forceinline__ void cp_wait() {
    asm volatile("cp.async.wait_group %0;" :: "n"(N) : "memory");
}
__device__ __forceinline__ void ldsm4(uint32_t (&r)[4], uint32_t addr) {
    asm volatile("ldmatrix.sync.aligned.m8n8.x4.shared.b16 {%0,%1,%2,%3}, [%4];"
                 : "=r"(r[0]), "=r"(r[1]), "=r"(r[2]), "=r"(r[3]) : "r"(addr));
}
__device__ __forceinline__ void ldsm4p(uint32_t* r, uint32_t addr) {
    asm volatile("ldmatrix.sync.aligned.m8n8.x4.shared.b16 {%0,%1,%2,%3}, [%4];"
                 : "=r"(r[0]), "=r"(r[1]), "=r"(r[2]), "=r"(r[3]) : "r"(addr));
}
__device__ __forceinline__ void ldsm4t(uint32_t* r, uint32_t addr) {
    asm volatile("ldmatrix.sync.aligned.m8n8.x4.trans.shared.b16 {%0,%1,%2,%3}, [%4];"
                 : "=r"(r[0]), "=r"(r[1]), "=r"(r[2]), "=r"(r[3]) : "r"(addr));
}
__device__ __forceinline__ void mma_f16(float (&c)[4],
                                        uint32_t a0, uint32_t a1, uint32_t a2, uint32_t a3,
                                        uint32_t b0, uint32_t b1) {
    asm volatile(
        "mma.sync.aligned.m16n8k16.row.col.f32.f16.f16.f32 "
        "{%0,%1,%2,%3}, {%4,%5,%6,%7}, {%8,%9}, {%0,%1,%2,%3};"
        : "+f"(c[0]), "+f"(c[1]), "+f"(c[2]), "+f"(c[3])
        : "r"(a0), "r"(a1), "r"(a2), "r"(a3), "r"(b0), "r"(b1));
}
__device__ __forceinline__ uint32_t cvt16x2(float hi, float lo) {
    uint32_t d;
    asm("cvt.rn.f16x2.f32 %0, %1, %2;" : "=r"(d) : "f"(hi), "f"(lo));
    return d;
}
__device__ __forceinline__ float ex2f(float x) {
    float r;
    asm("ex2.approx.ftz.f32 %0, %1;" : "=f"(r) : "f"(x));
    return r;
}

// ---------------------------------------------------------------------------
// pre-pass: f32 -> f16 convert (straight) and transpose-convert for weights
// ---------------------------------------------------------------------------
__global__ __launch_bounds__(256) void cvt_kernel(const float4* __restrict__ s,
                                                  uint2* __restrict__ d, int n4)
{
    int i = blockIdx.x * 256 + threadIdx.x;
    if (i < n4) {
        float4 v = s[i];
        d[i] = make_uint2(cvt16x2(v.y, v.x), cvt16x2(v.w, v.z));
    }
}

// w[K][N] f32 -> wt[N][K] f16
__global__ __launch_bounds__(256) void transcvt_kernel(const float* __restrict__ w,
                                                       __half* __restrict__ wt,
                                                       int K, int N)
{
    __shared__ float t[32][33];
    const int n0 = blockIdx.x * 32, k0 = blockIdx.y * 32;
    const int tx = threadIdx.x & 31, ty = threadIdx.x >> 5;
#pragma unroll
    for (int i = 0; i < 4; i++)
        t[ty + 8 * i][tx] = w[(size_t)(k0 + ty + 8 * i) * N + n0 + tx];
    __syncthreads();
#pragma unroll
    for (int i = 0; i < 4; i++)
        wt[(size_t)(n0 + ty + 8 * i) * K + k0 + tx] = __float2half_rn(t[tx][ty + 8 * i]);
}

// ---------------------------------------------------------------------------
// fp16 mma GEMM: C[M,N] = A[M,K] @ Bt[N,K]^T (+bias).
// 128x128 CTA tile, BK=64, 8 warps (2m x 4n), cp.async double-buffered smem.
// Smem rows = 128B (64 f16), 16B chunks XOR-swizzled: chunk c -> c ^ (row&7).
// ---------------------------------------------------------------------------
static constexpr int GEMM_SMEM = 4 * 16384;   // A0,A1,B0,B1

template <bool OUT_F32>
__global__ __launch_bounds__(256)
void gemm_h(const __half* __restrict__ A, const __half* __restrict__ Bt,
            const float* __restrict__ bias, void* __restrict__ Cv,
            int M, int N, int K)
{
    extern __shared__ char sm[];
    const uint32_t sb = smem_u32(sm);

    const int tid  = threadIdx.x;
    const int wid  = tid >> 5;
    const int lane = tid & 31;
    const int wm   = wid >> 2;
    const int wn   = wid & 3;
    const int bRow = blockIdx.y * 128;
    const int bCol = blockIdx.x * 128;

    const int crow = tid >> 1;
    const int cc0  = (tid & 1) * 4;
    const __half* Arow = A  + (size_t)(bRow + crow) * K;
    const __half* Brow = Bt + (size_t)(bCol + crow) * K;

    const int r8 = lane & 7;
    const int hA = (lane >> 3) & 1, gA = (lane >> 4) & 1;
    const int gB = (lane >> 3) & 1, hB = (lane >> 4) & 1;

    float acc[4][4][4];
#pragma unroll
    for (int i = 0; i < 4; i++)
#pragma unroll
        for (int j = 0; j < 4; j++)
#pragma unroll
            for (int v = 0; v < 4; v++) acc[i][j][v] = 0.f;

    auto stage = [&](int kc, int buf) {
        const uint32_t ab = sb + (uint32_t)buf * 16384u;
        const uint32_t bb = sb + 32768u + (uint32_t)buf * 16384u;
        const uint32_t soff = (uint32_t)crow * 128u;
#pragma unroll
        for (int i = 0; i < 4; i++) {
            int c = cc0 + i;
            uint32_t sw = soff + 16u * (uint32_t)(c ^ (crow & 7));
            cp_async16(ab + sw, Arow + kc * 64 + c * 8);
            cp_async16(bb + sw, Brow + kc * 64 + c * 8);
        }
        cp_commit();
    };

    const int NC = K / 64;
    stage(0, 0);

#pragma unroll 1
    for (int kc = 0; kc < NC; kc++) {
        const int buf = kc & 1;
        if (kc + 1 < NC) { stage(kc + 1, buf ^ 1); cp_wait<1>(); }
        else             { cp_wait<0>(); }
        __syncthreads();

        const uint32_t aB = sb + (uint32_t)buf * 16384u;
        const uint32_t bB = sb + 32768u + (uint32_t)buf * 16384u;
#pragma unroll
        for (int ks = 0; ks < 4; ks++) {
            uint32_t breg[2][4];
#pragma unroll
            for (int np = 0; np < 2; np++) {
                int nrow = wn * 32 + np * 16 + hB * 8 + r8;
                int ch   = 2 * ks + gB;
                ldsm4(breg[np], bB + (uint32_t)nrow * 128u + 16u * (uint32_t)(ch ^ (nrow & 7)));
            }
#pragma unroll
            for (int mi = 0; mi < 4; mi++) {
                uint32_t areg[4];
                int arow = wm * 64 + mi * 16 + hA * 8 + r8;
                int ch   = 2 * ks + gA;
                ldsm4(areg, aB + (uint32_t)arow * 128u + 16u * (uint32_t)(ch ^ (arow & 7)));
#pragma unroll
                for (int ni = 0; ni < 4; ni++) {
                    const uint32_t* br = breg[ni >> 1];
                    int off = (ni & 1) * 2;
                    mma_f16(acc[mi][ni], areg[0], areg[1], areg[2], areg[3],
                            br[off], br[off + 1]);
                }
            }
        }
        __syncthreads();
    }

    // epilogue
    const int erow = lane >> 2;
    const int ecol = (lane & 3) * 2;
#pragma unroll
    for (int mi = 0; mi < 4; mi++) {
#pragma unroll
        for (int ni = 0; ni < 4; ni++) {
            int col = bCol + wn * 32 + ni * 8 + ecol;
            int r0  = bRow + wm * 64 + mi * 16 + erow;
            if (OUT_F32) {
                float* C = (float*)Cv;
                float bx = bias[col], by = bias[col + 1];
                float2 v0 = { acc[mi][ni][0] + bx, acc[mi][ni][1] + by };
                float2 v1 = { acc[mi][ni][2] + bx, acc[mi][ni][3] + by };
                *(float2*)(C + (size_t)r0 * N + col) = v0;
                *(float2*)(C + (size_t)(r0 + 8) * N + col) = v1;
            } else {
                __half* C = (__half*)Cv;
                *(uint32_t*)(C + (size_t)r0 * N + col) =
                    cvt16x2(acc[mi][ni][1], acc[mi][ni][0]);
                *(uint32_t*)(C + (size_t)(r0 + 8) * N + col) =
                    cvt16x2(acc[mi][ni][3], acc[mi][ni][2]);
            }
        }
    }
}

// ---------------------------------------------------------------------------
// Tensor-core flash attention, fp16 in/out, cp.async double-buffered K/V.
// CTA: 8 warps, 128 query rows (16/warp), 64-key tiles.
// ---------------------------------------------------------------------------
__global__ __launch_bounds__(256) void attn_fa()
{
    const int b    = blockIdx.z;
    const int h    = blockIdx.y;
    const int tid  = threadIdx.x;
    const int warp = tid >> 5;
    const int lane = tid & 31;

    // k0 @0, k1 @8192, v0 @16384, v1 @24576
    __shared__ __align__(16) char sm[32768];
    const uint32_t base = smem_u32(sm);

    const __half* qkvB = g_qkv_h + (size_t)b * SEQ * (3 * DIM);

    const int rloc    = warp * 16 + (lane >> 2);
    const int grow_lo = blockIdx.x * 128 + rloc;
    const __half* qp_lo = qkvB + (size_t)grow_lo * (3 * DIM) + h * HD;
    const __half* qp_hi = qp_lo + (size_t)8 * (3 * DIM);

    uint32_t qf[4][4];
#pragma unroll
    for (int j = 0; j < 4; j++) {
        int k0 = j * 16 + 2 * (lane & 3);
        qf[j][0] = *(const uint32_t*)(qp_lo + k0);
        qf[j][1] = *(const uint32_t*)(qp_hi + k0);
        qf[j][2] = *(const uint32_t*)(qp_lo + k0 + 8);
        qf[j][3] = *(const uint32_t*)(qp_hi + k0 + 8);
    }

    float O[8][4];
#pragma unroll
    for (int i = 0; i < 8; i++)
#pragma unroll
        for (int c = 0; c < 4; c++) O[i][c] = 0.f;
    float lacc[4] = { 0.f, 0.f, 0.f, 0.f };
    float m_lo = -1e30f, m_hi = -1e30f;

    auto stage = [&](int j0, int buf) {
#pragma unroll
        for (int i = 0; i < 2; i++) {
            int id  = i * 256 + tid;
            int row = id >> 3, c = id & 7;
            const __half* kr = qkvB + (size_t)(j0 + row) * (3 * DIM) + DIM + h * HD + c * 8;
            uint32_t dst = base + (uint32_t)buf * 8192u +
                           (uint32_t)row * 128u + 16u * (uint32_t)(c ^ (row & 7));
            cp_async16(dst, kr);                 // K
            cp_async16(dst + 16384u, kr + DIM);  // V
        }
        cp_commit();
    };

    const uint32_t ONES = 0x3C003C00u;
    stage(0, 0);

#pragma unroll 1
    for (int t = 0; t < SEQ / 64; t++) {
        const int buf = t & 1;
        if (t + 1 < SEQ / 64) { stage((t + 1) * 64, buf ^ 1); cp_wait<1>(); }
        else                  { cp_wait<0>(); }
        __syncthreads();

        const uint32_t kB = base + (uint32_t)buf * 8192u;
        const uint32_t vB = kB + 16384u;

        // ---- S = Q K^T ----
        float S[8][4];
#pragma unroll
        for (int nt = 0; nt < 8; nt++)
#pragma unroll
            for (int c = 0; c < 4; c++) S[nt][c] = 0.f;

#pragma unroll
        for (int nt = 0; nt < 8; nt++) {
            uint32_t bk[8];
#pragma unroll
            for (int ks2 = 0; ks2 < 2; ks2++) {
                int mrow  = 8 * nt + (lane & 7);
                int chunk = ks2 * 4 + (lane >> 3);
                ldsm4p(&bk[ks2 * 4],
                       kB + (uint32_t)mrow * 128u + 16u * (uint32_t)(chunk ^ (mrow & 7)));
            }
            mma_f16(S[nt], qf[0][0], qf[0][1], qf[0][2], qf[0][3], bk[0], bk[1]);
            mma_f16(S[nt], qf[1][0], qf[1][1], qf[1][2], qf[1][3], bk[2], bk[3]);
            mma_f16(S[nt], qf[2][0], qf[2][1], qf[2][2], qf[2][3], bk[4], bk[5]);
            mma_f16(S[nt], qf[3][0], qf[3][1], qf[3][2], qf[3][3], bk[6], bk[7]);
        }

        // ---- online softmax (base 2) ----
        float tmax_lo = -1e30f, tmax_hi = -1e30f;
#pragma unroll
        for (int nt = 0; nt < 8; nt++) {
            S[nt][0] *= CSC; S[nt][1] *= CSC; S[nt][2] *= CSC; S[nt][3] *= CSC;
            tmax_lo = fmaxf(tmax_lo, fmaxf(S[nt][0], S[nt][1]));
            tmax_hi = fmaxf(tmax_hi, fmaxf(S[nt][2], S[nt][3]));
        }
        tmax_lo = fmaxf(tmax_lo, __shfl_xor_sync(0xffffffffu, tmax_lo, 1));
        tmax_lo = fmaxf(tmax_lo, __shfl_xor_sync(0xffffffffu, tmax_lo, 2));
        tmax_hi = fmaxf(tmax_hi, __shfl_xor_sync(0xffffffffu, tmax_hi, 1));
        tmax_hi = fmaxf(tmax_hi, __shfl_xor_sync(0xffffffffu, tmax_hi, 2));

        const float mn_lo = fmaxf(m_lo, tmax_lo);
        const float mn_hi = fmaxf(m_hi, tmax_hi);
        const float al = ex2f(m_lo - mn_lo);
        const float ah = ex2f(m_hi - mn_hi);
        m_lo = mn_lo; m_hi = mn_hi;

#pragma unroll
        for (int nt = 0; nt < 8; nt++) {
            O[nt][0] *= al; O[nt][1] *= al; O[nt][2] *= ah; O[nt][3] *= ah;
        }
        lacc[0] *= al; lacc[1] *= al; lacc[2] *= ah; lacc[3] *= ah;

        uint32_t P[8][2];
#pragma unroll
        for (int nt = 0; nt < 8; nt++) {
            float p0 = ex2f(S[nt][0] - mn_lo);
            float p1 = ex2f(S[nt][1] - mn_lo);
            float p2 = ex2f(S[nt][2] - mn_hi);
            float p3 = ex2f(S[nt][3] - mn_hi);
            P[nt][0] = cvt16x2(p1, p0);
            P[nt][1] = cvt16x2(p3, p2);
        }

        // l += P @ ones
#pragma unroll
        for (int ks = 0; ks < 4; ks++)
            mma_f16(lacc, P[2 * ks][0], P[2 * ks][1], P[2 * ks + 1][0], P[2 * ks + 1][1],
                    ONES, ONES);

        // ---- O += P @ V ----
#pragma unroll
        for (int nt = 0; nt < 8; nt++) {
            uint32_t bv[8];
#pragma unroll
            for (int kp = 0; kp < 2; kp++) {
                int mrow = 32 * kp + 8 * (lane >> 3) + (lane & 7);
                ldsm4t(&bv[kp * 4],
                       vB + (uint32_t)mrow * 128u + 16u * (uint32_t)(nt ^ (mrow & 7)));
            }
#pragma unroll
            for (int ks = 0; ks < 4; ks++)
                mma_f16(O[nt], P[2 * ks][0], P[2 * ks][1], P[2 * ks + 1][0], P[2 * ks + 1][1],
                        bv[2 * ks], bv[2 * ks + 1]);
        }
        __syncthreads();
    }

    // ---- finalize: O / l, write fp16 ----
    const float inv_lo = 1.f / lacc[0];
    const float inv_hi = 1.f / lacc[2];
    __half* orow_lo = g_attn_h + ((size_t)(b * SEQ) + grow_lo) * DIM + h * HD;
    __half* orow_hi = orow_lo + (size_t)8 * DIM;
#pragma unroll
    for (int nt = 0; nt < 8; nt++) {
        int col = nt * 8 + 2 * (lane & 3);
        *(uint32_t*)(orow_lo + col) = cvt16x2(O[nt][1] * inv_lo, O[nt][0] * inv_lo);
        *(uint32_t*)(orow_hi + col) = cvt16x2(O[nt][3] * inv_hi, O[nt][2] * inv_hi);
    }
}

// ---------------------------------------------------------------------------
extern "C" void kernel_launch(void* const* d_in, const int* in_sizes, int n_in,
                              void* d_out, int out_size)
{
    const float* x     = (const float*)d_in[0];
    const float* w_qkv = (const float*)d_in[1];
    const float* w_out = (const float*)d_in[2];
    const float* b_out = (const float*)d_in[3];
    float*       out   = (float*)d_out;

    __half *xh, *wqkvh, *wouth, *qkvh, *attnh;
    cudaGetSymbolAddress((void**)&xh,    g_x_h);
    cudaGetSymbolAddress((void**)&wqkvh, g_wqkv_h);
    cudaGetSymbolAddress((void**)&wouth, g_wout_h);
    cudaGetSymbolAddress((void**)&qkvh,  g_qkv_h);
    cudaGetSymbolAddress((void**)&attnh, g_attn_h);

    cudaFuncSetAttribute(gemm_h<false>,
                         cudaFuncAttributeMaxDynamicSharedMemorySize, GEMM_SMEM);
    cudaFuncSetAttribute(gemm_h<true>,
                         cudaFuncAttributeMaxDynamicSharedMemorySize, GEMM_SMEM);

    const int M = MROWS;  // 8192

    // pre-pass conversions
    {
        int n4 = M * DIM / 4;
        cvt_kernel<<<(n4 + 255) / 256, 256>>>((const float4*)x, (uint2*)xh, n4);
        transcvt_kernel<<<dim3(3 * DIM / 32, DIM / 32), 256>>>(w_qkv, wqkvh, DIM, 3 * DIM);
        transcvt_kernel<<<dim3(DIM / 32, DIM / 32), 256>>>(w_out, wouth, DIM, DIM);
    }

    // 1) QKV projection -> fp16
    gemm_h<false><<<dim3(3 * DIM / 128, M / 128), 256, GEMM_SMEM>>>(
        xh, wqkvh, nullptr, qkvh, M, 3 * DIM, DIM);

    // 2) attention (fp16 in/out)
    attn_fa<<<dim3(SEQ / 128, NH, BATCH), 256>>>();

    // 3) output projection + bias -> f32
    gemm_h<true><<<dim3(DIM / 128, M / 128), 256, GEMM_SMEM>>>(
        attnh, wouth, b_out, out, M, DIM, DIM);
}

// round 7
// speedup vs baseline: 8.3960x; 1.0436x over previous
#include <cuda_runtime.h>
#include <cuda_fp16.h>
#include <cstdint>
#include <math.h>

#define DIM   1024
#define NH    16
#define HD    64
#define BATCH 4
#define SEQ   2048
#define CSC   0.18033688011112042f   /* 64^-0.5 * log2(e) */

#define MROWS (BATCH * SEQ)          /* 8192 */

__device__ __half g_x_h   [(size_t)MROWS * DIM];
__device__ __half g_wqkv_h[(size_t)3 * DIM * DIM];    // [N][K]
__device__ __half g_wout_h[(size_t)DIM * DIM];        // [N][K]
__device__ __half g_qkv_h [(size_t)MROWS * 3 * DIM];
__device__ __half g_attn_h[(size_t)MROWS * DIM];

// ---------------------------------------------------------------------------
// helpers
// ---------------------------------------------------------------------------
__device__ __forceinline__ uint32_t smem_u32(const void* p) {
    uint32_t a;
    asm("{ .reg .u64 t; cvta.to.shared.u64 t, %1; cvt.u32.u64 %0, t; }"
        : "=r"(a) : "l"(p));
    return a;
}
__device__ __forceinline__ void cp_async16(uint32_t dst, const void* src) {
    asm volatile("cp.async.cg.shared.global [%0], [%1], 16;"
                 :: "r"(dst), "l"(src) : "memory");
}
__device__ __forceinline__ void cp_commit() {
    asm volatile("cp.async.commit_group;" ::: "memory");
}
template <int N>
__device__ __forceinline__ void cp_wait() {
    asm volatile("cp.async.wait_group %0;" :: "n"(N) : "memory");
}
__device__ __forceinline__ void ldsm4(uint32_t (&r)[4], uint32_t addr) {
    asm volatile("ldmatrix.sync.aligned.m8n8.x4.shared.b16 {%0,%1,%2,%3}, [%4];"
                 : "=r"(r[0]), "=r"(r[1]), "=r"(r[2]), "=r"(r[3]) : "r"(addr));
}
__device__ __forceinline__ void ldsm4p(uint32_t* r, uint32_t addr) {
    asm volatile("ldmatrix.sync.aligned.m8n8.x4.shared.b16 {%0,%1,%2,%3}, [%4];"
                 : "=r"(r[0]), "=r"(r[1]), "=r"(r[2]), "=r"(r[3]) : "r"(addr));
}
__device__ __forceinline__ void ldsm4t(uint32_t* r, uint32_t addr) {
    asm volatile("ldmatrix.sync.aligned.m8n8.x4.trans.shared.b16 {%0,%1,%2,%3}, [%4];"
                 : "=r"(r[0]), "=r"(r[1]), "=r"(r[2]), "=r"(r[3]) : "r"(addr));
}
__device__ __forceinline__ void mma_f16(float (&c)[4],
                                        uint32_t a0, uint32_t a1, uint32_t a2, uint32_t a3,
                                        uint32_t b0, uint32_t b1) {
    asm volatile(
        "mma.sync.aligned.m16n8k16.row.col.f32.f16.f16.f32 "
        "{%0,%1,%2,%3}, {%4,%5,%6,%7}, {%8,%9}, {%0,%1,%2,%3};"
        : "+f"(c[0]), "+f"(c[1]), "+f"(c[2]), "+f"(c[3])
        : "r"(a0), "r"(a1), "r"(a2), "r"(a3), "r"(b0), "r"(b1));
}
__device__ __forceinline__ uint32_t cvt16x2(float hi, float lo) {
    uint32_t d;
    asm("cvt.rn.f16x2.f32 %0, %1, %2;" : "=r"(d) : "f"(hi), "f"(lo));
    return d;
}
__device__ __forceinline__ float ex2f(float x) {
    float r;
    asm("ex2.approx.ftz.f32 %0, %1;" : "=f"(r) : "f"(x));
    return r;
}

// ---------------------------------------------------------------------------
// pre-pass converts
// ---------------------------------------------------------------------------
__global__ __launch_bounds__(256) void cvt_kernel(const float4* __restrict__ s,
                                                  uint2* __restrict__ d, int n4)
{
    int i = blockIdx.x * 256 + threadIdx.x;
    if (i < n4) {
        float4 v = s[i];
        d[i] = make_uint2(cvt16x2(v.y, v.x), cvt16x2(v.w, v.z));
    }
}

__global__ __launch_bounds__(256) void transcvt_kernel(const float* __restrict__ w,
                                                       __half* __restrict__ wt,
                                                       int K, int N)
{
    __shared__ float t[32][33];
    const int n0 = blockIdx.x * 32, k0 = blockIdx.y * 32;
    const int tx = threadIdx.x & 31, ty = threadIdx.x >> 5;
#pragma unroll
    for (int i = 0; i < 4; i++)
        t[ty + 8 * i][tx] = w[(size_t)(k0 + ty + 8 * i) * N + n0 + tx];
    __syncthreads();
#pragma unroll
    for (int i = 0; i < 4; i++)
        wt[(size_t)(n0 + ty + 8 * i) * K + k0 + tx] = __float2half_rn(t[tx][ty + 8 * i]);
}

// ---------------------------------------------------------------------------
// fp16 mma GEMM, 128x128x(BK=64), 3-stage cp.async ring, 1 barrier/chunk.
// smem per stage: A 16KB + B 16KB. A @ s*16384, B @ 49152 + s*16384.
// ---------------------------------------------------------------------------
static constexpr int GEMM_SMEM = 6 * 16384;   // 96KB

template <bool OUT_F32>
__global__ __launch_bounds__(256)
void gemm_h(const __half* __restrict__ A, const __half* __restrict__ Bt,
            const float* __restrict__ bias, void* __restrict__ Cv,
            int M, int N, int K)
{
    extern __shared__ char sm[];
    const uint32_t sb = smem_u32(sm);

    const int tid  = threadIdx.x;
    const int wid  = tid >> 5;
    const int lane = tid & 31;
    const int wm   = wid >> 2;
    const int wn   = wid & 3;
    const int bRow = blockIdx.y * 128;
    const int bCol = blockIdx.x * 128;

    const int crow = tid >> 1;
    const int cc0  = (tid & 1) * 4;
    const __half* Arow = A  + (size_t)(bRow + crow) * K;
    const __half* Brow = Bt + (size_t)(bCol + crow) * K;

    const int r8 = lane & 7;
    const int hA = (lane >> 3) & 1, gA = (lane >> 4) & 1;
    const int gB = (lane >> 3) & 1, hB = (lane >> 4) & 1;

    float acc[4][4][4];
#pragma unroll
    for (int i = 0; i < 4; i++)
#pragma unroll
        for (int j = 0; j < 4; j++)
#pragma unroll
            for (int v = 0; v < 4; v++) acc[i][j][v] = 0.f;

    auto stage = [&](int kc, int s) {
        const uint32_t ab = sb + (uint32_t)s * 16384u;
        const uint32_t bb = sb + 49152u + (uint32_t)s * 16384u;
        const uint32_t soff = (uint32_t)crow * 128u;
#pragma unroll
        for (int i = 0; i < 4; i++) {
            int c = cc0 + i;
            uint32_t sw = soff + 16u * (uint32_t)(c ^ (crow & 7));
            cp_async16(ab + sw, Arow + kc * 64 + c * 8);
            cp_async16(bb + sw, Brow + kc * 64 + c * 8);
        }
        cp_commit();
    };

    const int NC = K / 64;
    stage(0, 0);
    stage(1, 1);

#pragma unroll 1
    for (int kc = 0; kc < NC; kc++) {
        const int s = kc % 3;
        if (kc < NC - 1) cp_wait<1>();
        else             cp_wait<0>();
        __syncthreads();

        const uint32_t aB = sb + (uint32_t)s * 16384u;
        const uint32_t bB = sb + 49152u + (uint32_t)s * 16384u;
#pragma unroll
        for (int ks = 0; ks < 4; ks++) {
            uint32_t breg[2][4];
#pragma unroll
            for (int np = 0; np < 2; np++) {
                int nrow = wn * 32 + np * 16 + hB * 8 + r8;
                int ch   = 2 * ks + gB;
                ldsm4(breg[np], bB + (uint32_t)nrow * 128u + 16u * (uint32_t)(ch ^ (nrow & 7)));
            }
#pragma unroll
            for (int mi = 0; mi < 4; mi++) {
                uint32_t areg[4];
                int arow = wm * 64 + mi * 16 + hA * 8 + r8;
                int ch   = 2 * ks + gA;
                ldsm4(areg, aB + (uint32_t)arow * 128u + 16u * (uint32_t)(ch ^ (arow & 7)));
#pragma unroll
                for (int ni = 0; ni < 4; ni++) {
                    const uint32_t* br = breg[ni >> 1];
                    int off = (ni & 1) * 2;
                    mma_f16(acc[mi][ni], areg[0], areg[1], areg[2], areg[3],
                            br[off], br[off + 1]);
                }
            }
        }

        if (kc + 2 < NC) stage(kc + 2, (kc + 2) % 3);
    }

    // epilogue
    const int erow = lane >> 2;
    const int ecol = (lane & 3) * 2;
#pragma unroll
    for (int mi = 0; mi < 4; mi++) {
#pragma unroll
        for (int ni = 0; ni < 4; ni++) {
            int col = bCol + wn * 32 + ni * 8 + ecol;
            int r0  = bRow + wm * 64 + mi * 16 + erow;
            if (OUT_F32) {
                float* C = (float*)Cv;
                float bx = bias[col], by = bias[col + 1];
                float2 v0 = { acc[mi][ni][0] + bx, acc[mi][ni][1] + by };
                float2 v1 = { acc[mi][ni][2] + bx, acc[mi][ni][3] + by };
                *(float2*)(C + (size_t)r0 * N + col) = v0;
                *(float2*)(C + (size_t)(r0 + 8) * N + col) = v1;
            } else {
                __half* C = (__half*)Cv;
                *(uint32_t*)(C + (size_t)r0 * N + col) =
                    cvt16x2(acc[mi][ni][1], acc[mi][ni][0]);
                *(uint32_t*)(C + (size_t)(r0 + 8) * N + col) =
                    cvt16x2(acc[mi][ni][3], acc[mi][ni][2]);
            }
        }
    }
}

// ---------------------------------------------------------------------------
// Tensor-core flash attention, fp16 in/out, 3-stage cp.async ring.
// smem: K stages @ s*8192, V stages @ 24576 + s*8192  (48KB total).
// Softmax scale folded into Q fragments.
// ---------------------------------------------------------------------------
__global__ __launch_bounds__(256) void attn_fa()
{
    const int b    = blockIdx.z;
    const int h    = blockIdx.y;
    const int tid  = threadIdx.x;
    const int warp = tid >> 5;
    const int lane = tid & 31;

    __shared__ __align__(16) char sm[49152];
    const uint32_t base = smem_u32(sm);

    const __half* qkvB = g_qkv_h + (size_t)b * SEQ * (3 * DIM);

    const int rloc    = warp * 16 + (lane >> 2);
    const int grow_lo = blockIdx.x * 128 + rloc;
    const __half* qp_lo = qkvB + (size_t)grow_lo * (3 * DIM) + h * HD;
    const __half* qp_hi = qp_lo + (size_t)8 * (3 * DIM);

    const __half2 csc2 = __float2half2_rn(CSC);
    uint32_t qf[4][4];
#pragma unroll
    for (int j = 0; j < 4; j++) {
        int k0 = j * 16 + 2 * (lane & 3);
        __half2 v;
        v = __hmul2(*(const __half2*)(qp_lo + k0),     csc2); qf[j][0] = *(uint32_t*)&v;
        v = __hmul2(*(const __half2*)(qp_hi + k0),     csc2); qf[j][1] = *(uint32_t*)&v;
        v = __hmul2(*(const __half2*)(qp_lo + k0 + 8), csc2); qf[j][2] = *(uint32_t*)&v;
        v = __hmul2(*(const __half2*)(qp_hi + k0 + 8), csc2); qf[j][3] = *(uint32_t*)&v;
    }

    float O[8][4];
#pragma unroll
    for (int i = 0; i < 8; i++)
#pragma unroll
        for (int c = 0; c < 4; c++) O[i][c] = 0.f;
    float lacc[4] = { 0.f, 0.f, 0.f, 0.f };
    float m_lo = -1e30f, m_hi = -1e30f;

    auto stage = [&](int j0, int s) {
#pragma unroll
        for (int i = 0; i < 2; i++) {
            int id  = i * 256 + tid;
            int row = id >> 3, c = id & 7;
            const __half* kr = qkvB + (size_t)(j0 + row) * (3 * DIM) + DIM + h * HD + c * 8;
            uint32_t dst = base + (uint32_t)s * 8192u +
                           (uint32_t)row * 128u + 16u * (uint32_t)(c ^ (row & 7));
            cp_async16(dst, kr);                 // K
            cp_async16(dst + 24576u, kr + DIM);  // V
        }
        cp_commit();
    };

    const uint32_t ONES = 0x3C003C00u;
    const int NT = SEQ / 64;
    stage(0, 0);
    stage(64, 1);

#pragma unroll 1
    for (int t = 0; t < NT; t++) {
        const int s = t % 3;
        if (t < NT - 1) cp_wait<1>();
        else            cp_wait<0>();
        __syncthreads();

        const uint32_t kB = base + (uint32_t)s * 8192u;
        const uint32_t vB = kB + 24576u;

        // ---- S = (Q*CSC) K^T ----
        float S[8][4];
#pragma unroll
        for (int nt = 0; nt < 8; nt++)
#pragma unroll
            for (int c = 0; c < 4; c++) S[nt][c] = 0.f;

#pragma unroll
        for (int nt = 0; nt < 8; nt++) {
            uint32_t bk[8];
#pragma unroll
            for (int ks2 = 0; ks2 < 2; ks2++) {
                int mrow  = 8 * nt + (lane & 7);
                int chunk = ks2 * 4 + (lane >> 3);
                ldsm4p(&bk[ks2 * 4],
                       kB + (uint32_t)mrow * 128u + 16u * (uint32_t)(chunk ^ (mrow & 7)));
            }
            mma_f16(S[nt], qf[0][0], qf[0][1], qf[0][2], qf[0][3], bk[0], bk[1]);
            mma_f16(S[nt], qf[1][0], qf[1][1], qf[1][2], qf[1][3], bk[2], bk[3]);
            mma_f16(S[nt], qf[2][0], qf[2][1], qf[2][2], qf[2][3], bk[4], bk[5]);
            mma_f16(S[nt], qf[3][0], qf[3][1], qf[3][2], qf[3][3], bk[6], bk[7]);
        }

        // ---- online softmax (base 2; scale already folded into Q) ----
        float tmax_lo = -1e30f, tmax_hi = -1e30f;
#pragma unroll
        for (int nt = 0; nt < 8; nt++) {
            tmax_lo = fmaxf(tmax_lo, fmaxf(S[nt][0], S[nt][1]));
            tmax_hi = fmaxf(tmax_hi, fmaxf(S[nt][2], S[nt][3]));
        }
        tmax_lo = fmaxf(tmax_lo, __shfl_xor_sync(0xffffffffu, tmax_lo, 1));
        tmax_lo = fmaxf(tmax_lo, __shfl_xor_sync(0xffffffffu, tmax_lo, 2));
        tmax_hi = fmaxf(tmax_hi, __shfl_xor_sync(0xffffffffu, tmax_hi, 1));
        tmax_hi = fmaxf(tmax_hi, __shfl_xor_sync(0xffffffffu, tmax_hi, 2));

        const float mn_lo = fmaxf(m_lo, tmax_lo);
        const float mn_hi = fmaxf(m_hi, tmax_hi);
        const float al = ex2f(m_lo - mn_lo);
        const float ah = ex2f(m_hi - mn_hi);
        m_lo = mn_lo; m_hi = mn_hi;

#pragma unroll
        for (int nt = 0; nt < 8; nt++) {
            O[nt][0] *= al; O[nt][1] *= al; O[nt][2] *= ah; O[nt][3] *= ah;
        }
        lacc[0] *= al; lacc[1] *= al; lacc[2] *= ah; lacc[3] *= ah;

        uint32_t P[8][2];
#pragma unroll
        for (int nt = 0; nt < 8; nt++) {
            float p0 = ex2f(S[nt][0] - mn_lo);
            float p1 = ex2f(S[nt][1] - mn_lo);
            float p2 = ex2f(S[nt][2] - mn_hi);
            float p3 = ex2f(S[nt][3] - mn_hi);
            P[nt][0] = cvt16x2(p1, p0);
            P[nt][1] = cvt16x2(p3, p2);
        }

        // l += P @ ones
#pragma unroll
        for (int ks = 0; ks < 4; ks++)
            mma_f16(lacc, P[2 * ks][0], P[2 * ks][1], P[2 * ks + 1][0], P[2 * ks + 1][1],
                    ONES, ONES);

        // ---- O += P @ V ----
#pragma unroll
        for (int nt = 0; nt < 8; nt++) {
            uint32_t bv[8];
#pragma unroll
            for (int kp = 0; kp < 2; kp++) {
                int mrow = 32 * kp + 8 * (lane >> 3) + (lane & 7);
                ldsm4t(&bv[kp * 4],
                       vB + (uint32_t)mrow * 128u + 16u * (uint32_t)(nt ^ (mrow & 7)));
            }
#pragma unroll
            for (int ks = 0; ks < 4; ks++)
                mma_f16(O[nt], P[2 * ks][0], P[2 * ks][1], P[2 * ks + 1][0], P[2 * ks + 1][1],
                        bv[2 * ks], bv[2 * ks + 1]);
        }

        if (t + 2 < NT) stage((t + 2) * 64, (t + 2) % 3);
    }

    // ---- finalize ----
    const float inv_lo = 1.f / lacc[0];
    const float inv_hi = 1.f / lacc[2];
    __half* orow_lo = g_attn_h + ((size_t)(b * SEQ) + grow_lo) * DIM + h * HD;
    __half* orow_hi = orow_lo + (size_t)8 * DIM;
#pragma unroll
    for (int nt = 0; nt < 8; nt++) {
        int col = nt * 8 + 2 * (lane & 3);
        *(uint32_t*)(orow_lo + col) = cvt16x2(O[nt][1] * inv_lo, O[nt][0] * inv_lo);
        *(uint32_t*)(orow_hi + col) = cvt16x2(O[nt][3] * inv_hi, O[nt][2] * inv_hi);
    }
}

// ---------------------------------------------------------------------------
extern "C" void kernel_launch(void* const* d_in, const int* in_sizes, int n_in,
                              void* d_out, int out_size)
{
    const float* x     = (const float*)d_in[0];
    const float* w_qkv = (const float*)d_in[1];
    const float* w_out = (const float*)d_in[2];
    const float* b_out = (const float*)d_in[3];
    float*       out   = (float*)d_out;

    __half *xh, *wqkvh, *wouth, *qkvh, *attnh;
    cudaGetSymbolAddress((void**)&xh,    g_x_h);
    cudaGetSymbolAddress((void**)&wqkvh, g_wqkv_h);
    cudaGetSymbolAddress((void**)&wouth, g_wout_h);
    cudaGetSymbolAddress((void**)&qkvh,  g_qkv_h);
    cudaGetSymbolAddress((void**)&attnh, g_attn_h);

    cudaFuncSetAttribute(gemm_h<false>,
                         cudaFuncAttributeMaxDynamicSharedMemorySize, GEMM_SMEM);
    cudaFuncSetAttribute(gemm_h<true>,
                         cudaFuncAttributeMaxDynamicSharedMemorySize, GEMM_SMEM);

    const int M = MROWS;  // 8192

    {
        int n4 = M * DIM / 4;
        cvt_kernel<<<(n4 + 255) / 256, 256>>>((const float4*)x, (uint2*)xh, n4);
        transcvt_kernel<<<dim3(3 * DIM / 32, DIM / 32), 256>>>(w_qkv, wqkvh, DIM, 3 * DIM);
        transcvt_kernel<<<dim3(DIM / 32, DIM / 32), 256>>>(w_out, wouth, DIM, DIM);
    }

    gemm_h<false><<<dim3(3 * DIM / 128, M / 128), 256, GEMM_SMEM>>>(
        xh, wqkvh, nullptr, qkvh, M, 3 * DIM, DIM);

    attn_fa<<<dim3(SEQ / 128, NH, BATCH), 256>>>();

    gemm_h<true><<<dim3(DIM / 128, M / 128), 256, GEMM_SMEM>>>(
        attnh, wouth, b_out, out, M, DIM, DIM);
}

// round 8
// speedup vs baseline: 8.8364x; 1.0525x over previous
#include <cuda_runtime.h>
#include <cuda_fp16.h>
#include <cstdint>
#include <math.h>

#define DIM   1024
#define NH    16
#define HD    64
#define BATCH 4
#define SEQ   2048
#define CSC   0.18033688011112042f   /* 64^-0.5 * log2(e) */

#define MROWS (BATCH * SEQ)          /* 8192 */

__device__ __half g_x_h   [(size_t)MROWS * DIM];
__device__ __half g_wqkv_h[(size_t)3 * DIM * DIM];    // [N][K]
__device__ __half g_wout_h[(size_t)DIM * DIM];        // [N][K]
__device__ __half g_qkv_h [(size_t)MROWS * 3 * DIM];
__device__ __half g_attn_h[(size_t)MROWS * DIM];

// ---------------------------------------------------------------------------
// helpers
// ---------------------------------------------------------------------------
__device__ __forceinline__ uint32_t smem_u32(const void* p) {
    uint32_t a;
    asm("{ .reg .u64 t; cvta.to.shared.u64 t, %1; cvt.u32.u64 %0, t; }"
        : "=r"(a) : "l"(p));
    return a;
}
__device__ __forceinline__ void cp_async16(uint32_t dst, const void* src) {
    asm volatile("cp.async.cg.shared.global [%0], [%1], 16;"
                 :: "r"(dst), "l"(src) : "memory");
}
__device__ __forceinline__ void cp_commit() {
    asm volatile("cp.async.commit_group;" ::: "memory");
}
template <int N>
__device__ __forceinline__ void cp_wait() {
    asm volatile("cp.async.wait_group %0;" :: "n"(N) : "memory");
}
__device__ __forceinline__ void ldsm4(uint32_t (&r)[4], uint32_t addr) {
    asm volatile("ldmatrix.sync.aligned.m8n8.x4.shared.b16 {%0,%1,%2,%3}, [%4];"
                 : "=r"(r[0]), "=r"(r[1]), "=r"(r[2]), "=r"(r[3]) : "r"(addr));
}
__device__ __forceinline__ void ldsm4p(uint32_t* r, uint32_t addr) {
    asm volatile("ldmatrix.sync.aligned.m8n8.x4.shared.b16 {%0,%1,%2,%3}, [%4];"
                 : "=r"(r[0]), "=r"(r[1]), "=r"(r[2]), "=r"(r[3]) : "r"(addr));
}
__device__ __forceinline__ void ldsm4t(uint32_t* r, uint32_t addr) {
    asm volatile("ldmatrix.sync.aligned.m8n8.x4.trans.shared.b16 {%0,%1,%2,%3}, [%4];"
                 : "=r"(r[0]), "=r"(r[1]), "=r"(r[2]), "=r"(r[3]) : "r"(addr));
}
__device__ __forceinline__ void mma_f16(float (&c)[4],
                                        uint32_t a0, uint32_t a1, uint32_t a2, uint32_t a3,
                                        uint32_t b0, uint32_t b1) {
    asm volatile(
        "mma.sync.aligned.m16n8k16.row.col.f32.f16.f16.f32 "
        "{%0,%1,%2,%3}, {%4,%5,%6,%7}, {%8,%9}, {%0,%1,%2,%3};"
        : "+f"(c[0]), "+f"(c[1]), "+f"(c[2]), "+f"(c[3])
        : "r"(a0), "r"(a1), "r"(a2), "r"(a3), "r"(b0), "r"(b1));
}
__device__ __forceinline__ uint32_t cvt16x2(float hi, float lo) {
    uint32_t d;
    asm("cvt.rn.f16x2.f32 %0, %1, %2;" : "=r"(d) : "f"(hi), "f"(lo));
    return d;
}
__device__ __forceinline__ float ex2f(float x) {
    float r;
    asm("ex2.approx.ftz.f32 %0, %1;" : "=f"(r) : "f"(x));
    return r;
}

// ---------------------------------------------------------------------------
// pre-pass converts
// ---------------------------------------------------------------------------
__global__ __launch_bounds__(256) void cvt_kernel(const float4* __restrict__ s,
                                                  uint2* __restrict__ d, int n4)
{
    int i = blockIdx.x * 256 + threadIdx.x;
    if (i < n4) {
        float4 v = s[i];
        d[i] = make_uint2(cvt16x2(v.y, v.x), cvt16x2(v.w, v.z));
    }
}

__global__ __launch_bounds__(256) void transcvt_kernel(const float* __restrict__ w,
                                                       __half* __restrict__ wt,
                                                       int K, int N)
{
    __shared__ float t[32][33];
    const int n0 = blockIdx.x * 32, k0 = blockIdx.y * 32;
    const int tx = threadIdx.x & 31, ty = threadIdx.x >> 5;
#pragma unroll
    for (int i = 0; i < 4; i++)
        t[ty + 8 * i][tx] = w[(size_t)(k0 + ty + 8 * i) * N + n0 + tx];
    __syncthreads();
#pragma unroll
    for (int i = 0; i < 4; i++)
        wt[(size_t)(n0 + ty + 8 * i) * K + k0 + tx] = __float2half_rn(t[tx][ty + 8 * i]);
}

// ---------------------------------------------------------------------------
// fp16 mma GEMM, 128x128x(BK=64), 3-stage cp.async ring, 1 barrier/chunk,
// stage issued at chunk top (max prefetch distance).
// ---------------------------------------------------------------------------
static constexpr int GEMM_SMEM = 6 * 16384;   // 96KB

template <bool OUT_F32>
__global__ __launch_bounds__(256, 2)
void gemm_h(const __half* __restrict__ A, const __half* __restrict__ Bt,
            const float* __restrict__ bias, void* __restrict__ Cv,
            int M, int N, int K)
{
    extern __shared__ char sm[];
    const uint32_t sb = smem_u32(sm);

    const int tid  = threadIdx.x;
    const int wid  = tid >> 5;
    const int lane = tid & 31;
    const int wm   = wid >> 2;
    const int wn   = wid & 3;
    const int bRow = blockIdx.y * 128;
    const int bCol = blockIdx.x * 128;

    const int crow = tid >> 1;
    const int cc0  = (tid & 1) * 4;
    const __half* Arow = A  + (size_t)(bRow + crow) * K;
    const __half* Brow = Bt + (size_t)(bCol + crow) * K;

    const int r8 = lane & 7;
    const int hA = (lane >> 3) & 1, gA = (lane >> 4) & 1;
    const int gB = (lane >> 3) & 1, hB = (lane >> 4) & 1;

    float acc[4][4][4];
#pragma unroll
    for (int i = 0; i < 4; i++)
#pragma unroll
        for (int j = 0; j < 4; j++)
#pragma unroll
            for (int v = 0; v < 4; v++) acc[i][j][v] = 0.f;

    auto stage = [&](int kc, int s) {
        const uint32_t ab = sb + (uint32_t)s * 16384u;
        const uint32_t bb = sb + 49152u + (uint32_t)s * 16384u;
        const uint32_t soff = (uint32_t)crow * 128u;
#pragma unroll
        for (int i = 0; i < 4; i++) {
            int c = cc0 + i;
            uint32_t sw = soff + 16u * (uint32_t)(c ^ (crow & 7));
            cp_async16(ab + sw, Arow + kc * 64 + c * 8);
            cp_async16(bb + sw, Brow + kc * 64 + c * 8);
        }
        cp_commit();
    };

    const int NC = K / 64;
    stage(0, 0);
    stage(1, 1);

#pragma unroll 1
    for (int kc = 0; kc < NC; kc++) {
        const int s = kc % 3;
        if (kc < NC - 1) cp_wait<1>();
        else             cp_wait<0>();
        __syncthreads();

        // early prefetch: overwrites stage read in chunk kc-1 (barrier-proven done)
        if (kc + 2 < NC) stage(kc + 2, (kc + 2) % 3);

        const uint32_t aB = sb + (uint32_t)s * 16384u;
        const uint32_t bB = sb + 49152u + (uint32_t)s * 16384u;
#pragma unroll
        for (int ks = 0; ks < 4; ks++) {
            uint32_t breg[2][4];
#pragma unroll
            for (int np = 0; np < 2; np++) {
                int nrow = wn * 32 + np * 16 + hB * 8 + r8;
                int ch   = 2 * ks + gB;
                ldsm4(breg[np], bB + (uint32_t)nrow * 128u + 16u * (uint32_t)(ch ^ (nrow & 7)));
            }
#pragma unroll
            for (int mi = 0; mi < 4; mi++) {
                uint32_t areg[4];
                int arow = wm * 64 + mi * 16 + hA * 8 + r8;
                int ch   = 2 * ks + gA;
                ldsm4(areg, aB + (uint32_t)arow * 128u + 16u * (uint32_t)(ch ^ (arow & 7)));
#pragma unroll
                for (int ni = 0; ni < 4; ni++) {
                    const uint32_t* br = breg[ni >> 1];
                    int off = (ni & 1) * 2;
                    mma_f16(acc[mi][ni], areg[0], areg[1], areg[2], areg[3],
                            br[off], br[off + 1]);
                }
            }
        }
    }

    // epilogue
    const int erow = lane >> 2;
    const int ecol = (lane & 3) * 2;
#pragma unroll
    for (int mi = 0; mi < 4; mi++) {
#pragma unroll
        for (int ni = 0; ni < 4; ni++) {
            int col = bCol + wn * 32 + ni * 8 + ecol;
            int r0  = bRow + wm * 64 + mi * 16 + erow;
            if (OUT_F32) {
                float* C = (float*)Cv;
                float bx = bias[col], by = bias[col + 1];
                float2 v0 = { acc[mi][ni][0] + bx, acc[mi][ni][1] + by };
                float2 v1 = { acc[mi][ni][2] + bx, acc[mi][ni][3] + by };
                *(float2*)(C + (size_t)r0 * N + col) = v0;
                *(float2*)(C + (size_t)(r0 + 8) * N + col) = v1;
            } else {
                __half* C = (__half*)Cv;
                *(uint32_t*)(C + (size_t)r0 * N + col) =
                    cvt16x2(acc[mi][ni][1], acc[mi][ni][0]);
                *(uint32_t*)(C + (size_t)(r0 + 8) * N + col) =
                    cvt16x2(acc[mi][ni][3], acc[mi][ni][2]);
            }
        }
    }
}

// ---------------------------------------------------------------------------
// Tensor-core flash attention, fp16 in/out, 3-stage ring, early staging.
// smem: K stages @ s*8192, V stages @ 24576 + s*8192  (48KB total).
// ---------------------------------------------------------------------------
__global__ __launch_bounds__(256, 2) void attn_fa()
{
    const int b    = blockIdx.z;
    const int h    = blockIdx.y;
    const int tid  = threadIdx.x;
    const int warp = tid >> 5;
    const int lane = tid & 31;

    __shared__ __align__(16) char sm[49152];
    const uint32_t base = smem_u32(sm);

    const __half* qkvB = g_qkv_h + (size_t)b * SEQ * (3 * DIM);

    const int rloc    = warp * 16 + (lane >> 2);
    const int grow_lo = blockIdx.x * 128 + rloc;
    const __half* qp_lo = qkvB + (size_t)grow_lo * (3 * DIM) + h * HD;
    const __half* qp_hi = qp_lo + (size_t)8 * (3 * DIM);

    const __half2 csc2 = __float2half2_rn(CSC);
    uint32_t qf[4][4];
#pragma unroll
    for (int j = 0; j < 4; j++) {
        int k0 = j * 16 + 2 * (lane & 3);
        __half2 v;
        v = __hmul2(*(const __half2*)(qp_lo + k0),     csc2); qf[j][0] = *(uint32_t*)&v;
        v = __hmul2(*(const __half2*)(qp_hi + k0),     csc2); qf[j][1] = *(uint32_t*)&v;
        v = __hmul2(*(const __half2*)(qp_lo + k0 + 8), csc2); qf[j][2] = *(uint32_t*)&v;
        v = __hmul2(*(const __half2*)(qp_hi + k0 + 8), csc2); qf[j][3] = *(uint32_t*)&v;
    }

    float O[8][4];
#pragma unroll
    for (int i = 0; i < 8; i++)
#pragma unroll
        for (int c = 0; c < 4; c++) O[i][c] = 0.f;
    float lacc[4] = { 0.f, 0.f, 0.f, 0.f };
    float m_lo = -1e30f, m_hi = -1e30f;

    auto stage = [&](int j0, int s) {
#pragma unroll
        for (int i = 0; i < 2; i++) {
            int id  = i * 256 + tid;
            int row = id >> 3, c = id & 7;
            const __half* kr = qkvB + (size_t)(j0 + row) * (3 * DIM) + DIM + h * HD + c * 8;
            uint32_t dst = base + (uint32_t)s * 8192u +
                           (uint32_t)row * 128u + 16u * (uint32_t)(c ^ (row & 7));
            cp_async16(dst, kr);                 // K
            cp_async16(dst + 24576u, kr + DIM);  // V
        }
        cp_commit();
    };

    const uint32_t ONES = 0x3C003C00u;
    const int NT = SEQ / 64;
    stage(0, 0);
    stage(64, 1);

#pragma unroll 1
    for (int t = 0; t < NT; t++) {
        const int s = t % 3;
        if (t < NT - 1) cp_wait<1>();
        else            cp_wait<0>();
        __syncthreads();

        if (t + 2 < NT) stage((t + 2) * 64, (t + 2) % 3);

        const uint32_t kB = base + (uint32_t)s * 8192u;
        const uint32_t vB = kB + 24576u;

        // ---- S = (Q*CSC) K^T ----
        float S[8][4];
#pragma unroll
        for (int nt = 0; nt < 8; nt++)
#pragma unroll
            for (int c = 0; c < 4; c++) S[nt][c] = 0.f;

#pragma unroll
        for (int nt = 0; nt < 8; nt++) {
            uint32_t bk[8];
#pragma unroll
            for (int ks2 = 0; ks2 < 2; ks2++) {
                int mrow  = 8 * nt + (lane & 7);
                int chunk = ks2 * 4 + (lane >> 3);
                ldsm4p(&bk[ks2 * 4],
                       kB + (uint32_t)mrow * 128u + 16u * (uint32_t)(chunk ^ (mrow & 7)));
            }
            mma_f16(S[nt], qf[0][0], qf[0][1], qf[0][2], qf[0][3], bk[0], bk[1]);
            mma_f16(S[nt], qf[1][0], qf[1][1], qf[1][2], qf[1][3], bk[2], bk[3]);
            mma_f16(S[nt], qf[2][0], qf[2][1], qf[2][2], qf[2][3], bk[4], bk[5]);
            mma_f16(S[nt], qf[3][0], qf[3][1], qf[3][2], qf[3][3], bk[6], bk[7]);
        }

        // ---- online softmax (base 2) ----
        float tmax_lo = -1e30f, tmax_hi = -1e30f;
#pragma unroll
        for (int nt = 0; nt < 8; nt++) {
            tmax_lo = fmaxf(tmax_lo, fmaxf(S[nt][0], S[nt][1]));
            tmax_hi = fmaxf(tmax_hi, fmaxf(S[nt][2], S[nt][3]));
        }
        tmax_lo = fmaxf(tmax_lo, __shfl_xor_sync(0xffffffffu, tmax_lo, 1));
        tmax_lo = fmaxf(tmax_lo, __shfl_xor_sync(0xffffffffu, tmax_lo, 2));
        tmax_hi = fmaxf(tmax_hi, __shfl_xor_sync(0xffffffffu, tmax_hi, 1));
        tmax_hi = fmaxf(tmax_hi, __shfl_xor_sync(0xffffffffu, tmax_hi, 2));

        const float mn_lo = fmaxf(m_lo, tmax_lo);
        const float mn_hi = fmaxf(m_hi, tmax_hi);
        const float al = ex2f(m_lo - mn_lo);
        const float ah = ex2f(m_hi - mn_hi);
        m_lo = mn_lo; m_hi = mn_hi;

#pragma unroll
        for (int nt = 0; nt < 8; nt++) {
            O[nt][0] *= al; O[nt][1] *= al; O[nt][2] *= ah; O[nt][3] *= ah;
        }
        lacc[0] *= al; lacc[1] *= al; lacc[2] *= ah; lacc[3] *= ah;

        uint32_t P[8][2];
#pragma unroll
        for (int nt = 0; nt < 8; nt++) {
            float p0 = ex2f(S[nt][0] - mn_lo);
            float p1 = ex2f(S[nt][1] - mn_lo);
            float p2 = ex2f(S[nt][2] - mn_hi);
            float p3 = ex2f(S[nt][3] - mn_hi);
            P[nt][0] = cvt16x2(p1, p0);
            P[nt][1] = cvt16x2(p3, p2);
        }

        // l += P @ ones
#pragma unroll
        for (int ks = 0; ks < 4; ks++)
            mma_f16(lacc, P[2 * ks][0], P[2 * ks][1], P[2 * ks + 1][0], P[2 * ks + 1][1],
                    ONES, ONES);

        // ---- O += P @ V ----
#pragma unroll
        for (int nt = 0; nt < 8; nt++) {
            uint32_t bv[8];
#pragma unroll
            for (int kp = 0; kp < 2; kp++) {
                int mrow = 32 * kp + 8 * (lane >> 3) + (lane & 7);
                ldsm4t(&bv[kp * 4],
                       vB + (uint32_t)mrow * 128u + 16u * (uint32_t)(nt ^ (mrow & 7)));
            }
#pragma unroll
            for (int ks = 0; ks < 4; ks++)
                mma_f16(O[nt], P[2 * ks][0], P[2 * ks][1], P[2 * ks + 1][0], P[2 * ks + 1][1],
                        bv[2 * ks], bv[2 * ks + 1]);
        }
    }

    // ---- finalize ----
    const float inv_lo = 1.f / lacc[0];
    const float inv_hi = 1.f / lacc[2];
    __half* orow_lo = g_attn_h + ((size_t)(b * SEQ) + grow_lo) * DIM + h * HD;
    __half* orow_hi = orow_lo + (size_t)8 * DIM;
#pragma unroll
    for (int nt = 0; nt < 8; nt++) {
        int col = nt * 8 + 2 * (lane & 3);
        *(uint32_t*)(orow_lo + col) = cvt16x2(O[nt][1] * inv_lo, O[nt][0] * inv_lo);
        *(uint32_t*)(orow_hi + col) = cvt16x2(O[nt][3] * inv_hi, O[nt][2] * inv_hi);
    }
}

// ---------------------------------------------------------------------------
extern "C" void kernel_launch(void* const* d_in, const int* in_sizes, int n_in,
                              void* d_out, int out_size)
{
    const float* x     = (const float*)d_in[0];
    const float* w_qkv = (const float*)d_in[1];
    const float* w_out = (const float*)d_in[2];
    const float* b_out = (const float*)d_in[3];
    float*       out   = (float*)d_out;

    __half *xh, *wqkvh, *wouth, *qkvh, *attnh;
    cudaGetSymbolAddress((void**)&xh,    g_x_h);
    cudaGetSymbolAddress((void**)&wqkvh, g_wqkv_h);
    cudaGetSymbolAddress((void**)&wouth, g_wout_h);
    cudaGetSymbolAddress((void**)&qkvh,  g_qkv_h);
    cudaGetSymbolAddress((void**)&attnh, g_attn_h);

    cudaFuncSetAttribute(gemm_h<false>,
                         cudaFuncAttributeMaxDynamicSharedMemorySize, GEMM_SMEM);
    cudaFuncSetAttribute(gemm_h<true>,
                         cudaFuncAttributeMaxDynamicSharedMemorySize, GEMM_SMEM);

    const int M = MROWS;  // 8192

    {
        int n4 = M * DIM / 4;
        cvt_kernel<<<(n4 + 255) / 256, 256>>>((const float4*)x, (uint2*)xh, n4);
        transcvt_kernel<<<dim3(3 * DIM / 32, DIM / 32), 256>>>(w_qkv, wqkvh, DIM, 3 * DIM);
        transcvt_kernel<<<dim3(DIM / 32, DIM / 32), 256>>>(w_out, wouth, DIM, DIM);
    }

    gemm_h<false><<<dim3(3 * DIM / 128, M / 128), 256, GEMM_SMEM>>>(
        xh, wqkvh, nullptr, qkvh, M, 3 * DIM, DIM);

    attn_fa<<<dim3(SEQ / 128, NH, BATCH), 256>>>();

    gemm_h<true><<<dim3(DIM / 128, M / 128), 256, GEMM_SMEM>>>(
        attnh, wouth, b_out, out, M, DIM, DIM);
}